// round 4
// baseline (speedup 1.0000x reference)
#include <cuda_runtime.h>
#include <math.h>
#include <stdint.h>

// ---------------- problem constants ----------------
#define TT    2080
#define DM    512
#define NH    8
#define DH    64
#define DI    2048
#define NLAY  4
#define NMTOK 16
#define QL    2048

// ---------------- scratch ----------------
__device__ float g_w[TT * DM];
__device__ float g_pos[TT * DM];
__device__ float g_heads[TT * 3 * DM];
__device__ float g_r[TT * DM];
__device__ float g_av[TT * DM];
__device__ float g_tmp[TT * DM];
__device__ float g_ff1[TT * DI];

// ---------------- prep kernels ----------------
__global__ void build_w_kernel(const float* __restrict__ word_emb,
                               const float* __restrict__ mem) {
    int idx = blockIdx.x * blockDim.x + threadIdx.x;
    if (idx >= TT * DM) return;
    int row = idx / DM, c = idx % DM;
    float v;
    if (row < NMTOK)            v = mem[row * DM + c];
    else if (row < NMTOK + QL)  v = word_emb[(row - NMTOK) * DM + c];
    else                        v = mem[(row - NMTOK - QL) * DM + c];
    g_w[idx] = v;
}

__global__ void build_pos_kernel() {
    int idx = blockIdx.x * blockDim.x + threadIdx.x;
    if (idx >= TT * DM) return;
    int row = idx / DM, c = idx % DM;
    int f = (c < DM / 2) ? c : (c - DM / 2);
    double invf = exp(-((double)(2 * f) / (double)DM) * log(10000.0));
    double val = (double)(TT - 1 - row) * invf;
    g_pos[idx] = (float)((c < DM / 2) ? sin(val) : cos(val));
}

// ---------------- tf32 helpers ----------------
__device__ __forceinline__ void split_tf32(float x, uint32_t& hi, uint32_t& lo) {
    uint32_t h;
    asm("cvt.rna.tf32.f32 %0, %1;" : "=r"(h) : "f"(x));
    float r = x - __uint_as_float(h);
    uint32_t l;
    asm("cvt.rna.tf32.f32 %0, %1;" : "=r"(l) : "f"(r));
    hi = h; lo = l;
}

__device__ __forceinline__ void mma8(float (&c)[4], const uint32_t (&a)[4],
                                     const uint32_t (&b)[2]) {
    asm volatile(
        "mma.sync.aligned.m16n8k8.row.col.f32.tf32.tf32.f32 "
        "{%0,%1,%2,%3}, {%4,%5,%6,%7}, {%8,%9}, {%0,%1,%2,%3};"
        : "+f"(c[0]), "+f"(c[1]), "+f"(c[2]), "+f"(c[3])
        : "r"(a[0]), "r"(a[1]), "r"(a[2]), "r"(a[3]), "r"(b[0]), "r"(b[1]));
}

// ---------------- projection GEMM (3xTF32, NN) ----------------
#define LDA_S 36
#define LDB_NN 72

__global__ __launch_bounds__(256, 2)
void mma_gemm(const float* __restrict__ A, int lda,
              const float* __restrict__ B, int ldb,
              float* __restrict__ C, int ldc,
              const float* __restrict__ cbias, int doRelu,
              int M, int N, int K) {
    __shared__ float As[128 * LDA_S];
    __shared__ float Bs[32 * LDB_NN];

    const int bm = blockIdx.y * 128, bn = blockIdx.x * 64;
    const int tid = threadIdx.x;
    const int lane = tid & 31, warp = tid >> 5;
    const int wm = warp & 3, wn = warp >> 2;
    const int g4 = lane >> 2, l4 = lane & 3;

    float acc[2][4][4] = {};
    float4 pa[4], pb[2];

    auto loadA = [&](int k0) {
        const int r = tid >> 3, k4 = (tid & 7) * 4;
        #pragma unroll
        for (int p = 0; p < 4; p++) {
            int row = bm + p * 32 + r;
            float4 v = make_float4(0.f, 0.f, 0.f, 0.f);
            if (row < M) v = *reinterpret_cast<const float4*>(A + (size_t)row * lda + k0 + k4);
            pa[p] = v;
        }
    };
    auto loadB = [&](int k0) {
        const int r = tid >> 4, n4 = (tid & 15) * 4;
        #pragma unroll
        for (int p = 0; p < 2; p++) {
            int k = k0 + p * 16 + r;
            pb[p] = *reinterpret_cast<const float4*>(B + (size_t)k * ldb + bn + n4);
        }
    };
    auto storeAB = [&]() {
        {
            const int r = tid >> 3, k4 = (tid & 7) * 4;
            #pragma unroll
            for (int p = 0; p < 4; p++)
                *reinterpret_cast<float4*>(&As[(p * 32 + r) * LDA_S + k4]) = pa[p];
        }
        {
            const int r = tid >> 4, n4 = (tid & 15) * 4;
            #pragma unroll
            for (int p = 0; p < 2; p++)
                *reinterpret_cast<float4*>(&Bs[(p * 16 + r) * LDB_NN + n4]) = pb[p];
        }
    };

    loadA(0);
    loadB(0);

    for (int k0 = 0; k0 < K; k0 += 32) {
        storeAB();
        __syncthreads();
        if (k0 + 32 < K) { loadA(k0 + 32); loadB(k0 + 32); }

        #pragma unroll
        for (int ks = 0; ks < 4; ks++) {
            const int kk = ks * 8 + l4;
            uint32_t ah[2][4], al[2][4];
            #pragma unroll
            for (int am = 0; am < 2; am++) {
                int mb = wm * 32 + am * 16 + g4;
                split_tf32(As[mb * LDA_S + kk],           ah[am][0], al[am][0]);
                split_tf32(As[(mb + 8) * LDA_S + kk],     ah[am][1], al[am][1]);
                split_tf32(As[mb * LDA_S + kk + 4],       ah[am][2], al[am][2]);
                split_tf32(As[(mb + 8) * LDA_S + kk + 4], ah[am][3], al[am][3]);
            }
            uint32_t bh[4][2], bl[4][2];
            #pragma unroll
            for (int an = 0; an < 4; an++) {
                int nb = wn * 32 + an * 8 + g4;
                split_tf32(Bs[kk * LDB_NN + nb],       bh[an][0], bl[an][0]);
                split_tf32(Bs[(kk + 4) * LDB_NN + nb], bh[an][1], bl[an][1]);
            }
            #pragma unroll
            for (int am = 0; am < 2; am++)
                #pragma unroll
                for (int an = 0; an < 4; an++) {
                    mma8(acc[am][an], ah[am], bh[an]);
                    mma8(acc[am][an], ah[am], bl[an]);
                    mma8(acc[am][an], al[am], bh[an]);
                }
        }
        __syncthreads();
    }

    #pragma unroll
    for (int am = 0; am < 2; am++) {
        int row0 = bm + wm * 32 + am * 16 + g4;
        #pragma unroll
        for (int an = 0; an < 4; an++) {
            int col0 = bn + wn * 32 + an * 8 + 2 * l4;
            float v0 = acc[am][an][0], v1 = acc[am][an][1];
            float v2 = acc[am][an][2], v3 = acc[am][an][3];
            if (cbias) {
                float b0 = cbias[col0], b1 = cbias[col0 + 1];
                v0 += b0; v1 += b1; v2 += b0; v3 += b1;
            }
            if (doRelu) {
                v0 = fmaxf(v0, 0.f); v1 = fmaxf(v1, 0.f);
                v2 = fmaxf(v2, 0.f); v3 = fmaxf(v3, 0.f);
            }
            if (row0 < M) {
                C[(size_t)row0 * ldc + col0]     = v0;
                C[(size_t)row0 * ldc + col0 + 1] = v1;
            }
            if (row0 + 8 < M) {
                C[(size_t)(row0 + 8) * ldc + col0]     = v2;
                C[(size_t)(row0 + 8) * ldc + col0 + 1] = v3;
            }
        }
    }
}

// ---------------- fused flash-style relative attention ----------------
// CTA = (head h, pair p). p<16 -> query blocks {p, 31-p}; p=16 -> block 32.
// Per 64-row query block: stream 64-key tiles with online softmax.
// BDraw computed incrementally into a 4-slot rolling chunk ring:
//   BD[i,j] (j<=i) = Craw[di][jr], jr = TT-1-i+j.
// Mem-token corners (j>i unmasked) handled by scalar fixup.
#define PAD 68
#define TILE_F (64 * PAD)
#define ATTN_SMEM (10 * TILE_F * 4)   // bytes: Qw,Qr,Ks,Vs,Rs,Ps + 4 Craw slots

__global__ __launch_bounds__(128, 1)
void fused_attn_kernel(const float* __restrict__ heads,
                       const float* __restrict__ rbuf,
                       const float* __restrict__ rwb,
                       const float* __restrict__ rrb,
                       float* __restrict__ av) {
    extern __shared__ float sm[];
    float* Qw = sm;
    float* Qr = sm + TILE_F;
    float* Ks = sm + 2 * TILE_F;
    float* Vs = sm + 3 * TILE_F;
    float* Rs = sm + 4 * TILE_F;
    float* Ps = sm + 5 * TILE_F;
    float* Cw = sm + 6 * TILE_F;   // 4 slots of TILE_F

    const int h = blockIdx.x;
    const int p = blockIdx.y;
    const int tid = threadIdx.x;
    const int lane = tid & 31, warp = tid >> 5;
    const int g4 = lane >> 2, l4 = lane & 3;
    const int wr0 = warp * 16 + g4;

    int blist[2]; int nblk;
    if (p < 16) { blist[0] = p; blist[1] = 31 - p; nblk = 2; }
    else        { blist[0] = 32; nblk = 1; }

    for (int bi = 0; bi < nblk; bi++) {
        const int b = blist[bi];
        const int i0 = b * 64;
        const int validRows = min(64, TT - i0);
        const int njt = (b < 32) ? (b + 1) : 33;

        __syncthreads();
        // Load Q (+ biases) for this block
        for (int t = tid; t < 64 * 16; t += 128) {
            int r = t >> 4, c4 = (t & 15) * 4;
            int grow = i0 + r;
            float4 q = make_float4(0.f, 0.f, 0.f, 0.f);
            if (grow < TT)
                q = *(const float4*)(heads + (size_t)grow * (3 * DM) + h * DH + c4);
            float4 bw = *(const float4*)(rwb + h * DH + c4);
            float4 br = *(const float4*)(rrb + h * DH + c4);
            *(float4*)(Qw + r * PAD + c4) =
                make_float4(q.x + bw.x, q.y + bw.y, q.z + bw.z, q.w + bw.w);
            *(float4*)(Qr + r * PAD + c4) =
                make_float4(q.x + br.x, q.y + br.y, q.z + br.z, q.w + br.w);
        }
        __syncthreads();

        float o[8][4];
        #pragma unroll
        for (int a = 0; a < 8; a++) { o[a][0] = o[a][1] = o[a][2] = o[a][3] = 0.f; }
        float mrow[2] = {-1e30f, -1e30f};
        float lrow[2] = {0.f, 0.f};

        int nextChunk = max(0, TT - 64 - i0) >> 6;

        for (int jt = 0; jt < njt; jt++) {
            const int j0 = jt * 64;

            // compute any new BDraw chunks needed for this tile's window
            const int hiJr = min(TT - 1, TT - 1 - i0 + j0 + 63);
            const int chi = hiJr >> 6;
            while (nextChunk <= chi) {
                const int c = nextChunk;
                __syncthreads();
                for (int t = tid; t < 64 * 16; t += 128) {
                    int r = t >> 4, c4 = (t & 15) * 4;
                    int grow = c * 64 + r;
                    float4 v = make_float4(0.f, 0.f, 0.f, 0.f);
                    if (grow < TT)
                        v = *(const float4*)(rbuf + (size_t)grow * DM + h * DH + c4);
                    *(float4*)(Rs + r * PAD + c4) = v;
                }
                __syncthreads();
                float cacc[8][4];
                #pragma unroll
                for (int a = 0; a < 8; a++)
                    cacc[a][0] = cacc[a][1] = cacc[a][2] = cacc[a][3] = 0.f;
                #pragma unroll
                for (int ks = 0; ks < 8; ks++) {
                    int kk = ks * 8 + l4;
                    uint32_t ah[4], al[4];
                    split_tf32(Qr[wr0 * PAD + kk],           ah[0], al[0]);
                    split_tf32(Qr[(wr0 + 8) * PAD + kk],     ah[1], al[1]);
                    split_tf32(Qr[wr0 * PAD + kk + 4],       ah[2], al[2]);
                    split_tf32(Qr[(wr0 + 8) * PAD + kk + 4], ah[3], al[3]);
                    #pragma unroll
                    for (int an = 0; an < 8; an++) {
                        int nbv = an * 8 + g4;
                        uint32_t bh[2], bl[2];
                        split_tf32(Rs[nbv * PAD + kk],     bh[0], bl[0]);
                        split_tf32(Rs[nbv * PAD + kk + 4], bh[1], bl[1]);
                        mma8(cacc[an], ah, bh);
                        mma8(cacc[an], ah, bl);
                        mma8(cacc[an], al, bh);
                    }
                }
                float* slot = Cw + (c & 3) * TILE_F;
                #pragma unroll
                for (int an = 0; an < 8; an++) {
                    int col = an * 8 + 2 * l4;
                    slot[wr0 * PAD + col]           = cacc[an][0];
                    slot[wr0 * PAD + col + 1]       = cacc[an][1];
                    slot[(wr0 + 8) * PAD + col]     = cacc[an][2];
                    slot[(wr0 + 8) * PAD + col + 1] = cacc[an][3];
                }
                nextChunk++;
            }

            // load K, V tiles for this j-tile
            __syncthreads();
            for (int t = tid; t < 64 * 16; t += 128) {
                int r = t >> 4, c4 = (t & 15) * 4;
                int grow = j0 + r;
                float4 kv = make_float4(0.f, 0.f, 0.f, 0.f), vv = kv;
                if (grow < TT) {
                    kv = *(const float4*)(heads + (size_t)grow * (3 * DM) + DM + h * DH + c4);
                    vv = *(const float4*)(heads + (size_t)grow * (3 * DM) + 2 * DM + h * DH + c4);
                }
                *(float4*)(Ks + r * PAD + c4) = kv;
                *(float4*)(Vs + r * PAD + c4) = vv;
            }
            __syncthreads();

            // AC MMA: S = (q + rwb) . k^T
            float s[8][4];
            #pragma unroll
            for (int a = 0; a < 8; a++)
                s[a][0] = s[a][1] = s[a][2] = s[a][3] = 0.f;
            #pragma unroll
            for (int ks = 0; ks < 8; ks++) {
                int kk = ks * 8 + l4;
                uint32_t ah[4], al[4];
                split_tf32(Qw[wr0 * PAD + kk],           ah[0], al[0]);
                split_tf32(Qw[(wr0 + 8) * PAD + kk],     ah[1], al[1]);
                split_tf32(Qw[wr0 * PAD + kk + 4],       ah[2], al[2]);
                split_tf32(Qw[(wr0 + 8) * PAD + kk + 4], ah[3], al[3]);
                #pragma unroll
                for (int an = 0; an < 8; an++) {
                    int nbv = an * 8 + g4;
                    uint32_t bh[2], bl[2];
                    split_tf32(Ks[nbv * PAD + kk],     bh[0], bl[0]);
                    split_tf32(Ks[nbv * PAD + kk + 4], bh[1], bl[1]);
                    mma8(s[an], ah, bh);
                    mma8(s[an], ah, bl);
                    mma8(s[an], al, bh);
                }
            }

            // combine with rel-shifted BD, mask, scale; per-row tile max
            float tmax[2] = {-1e30f, -1e30f};
            #pragma unroll
            for (int an = 0; an < 8; an++) {
                #pragma unroll
                for (int e = 0; e < 4; e++) {
                    int rh = e >> 1;
                    int di = wr0 + rh * 8;
                    int dj = an * 8 + 2 * l4 + (e & 1);
                    int i = i0 + di, j = j0 + dj;
                    float v = -1e30f;
                    if (di < validRows && j < TT) {
                        int jmaxr = (i < NMTOK) ? (NMTOK - 1)
                                  : ((i >= TT - NMTOK) ? (TT - 1) : i);
                        if (j <= jmaxr) {
                            float bd;
                            if (j <= i) {
                                int jr = TT - 1 - i + j;
                                bd = Cw[((jr >> 6) & 3) * TILE_F + di * PAD + (jr & 63)];
                            } else if (j == i + 1) {
                                bd = 0.f;
                            } else {
                                const float* qrow = Qr + (di + 1) * PAD;
                                const float* rr = rbuf + (size_t)(j - i - 2) * DM + h * DH;
                                float accd = 0.f;
                                #pragma unroll 8
                                for (int d = 0; d < DH; d++) accd += qrow[d] * rr[d];
                                bd = accd;
                            }
                            v = (s[an][e] + bd) * 0.125f;
                        }
                    }
                    s[an][e] = v;
                    tmax[rh] = fmaxf(tmax[rh], v);
                }
            }
            #pragma unroll
            for (int rh = 0; rh < 2; rh++) {
                tmax[rh] = fmaxf(tmax[rh], __shfl_xor_sync(0xffffffffu, tmax[rh], 1));
                tmax[rh] = fmaxf(tmax[rh], __shfl_xor_sync(0xffffffffu, tmax[rh], 2));
            }

            // online softmax update
            float scale[2], lsum[2] = {0.f, 0.f};
            #pragma unroll
            for (int rh = 0; rh < 2; rh++) {
                float mnew = fmaxf(mrow[rh], tmax[rh]);
                scale[rh] = expf(mrow[rh] - mnew);
                mrow[rh] = mnew;
            }
            #pragma unroll
            for (int an = 0; an < 8; an++) {
                #pragma unroll
                for (int e = 0; e < 4; e++) {
                    int rh = e >> 1;
                    float ev = expf(s[an][e] - mrow[rh]);
                    s[an][e] = ev;
                    lsum[rh] += ev;
                }
            }
            #pragma unroll
            for (int rh = 0; rh < 2; rh++) {
                lsum[rh] += __shfl_xor_sync(0xffffffffu, lsum[rh], 1);
                lsum[rh] += __shfl_xor_sync(0xffffffffu, lsum[rh], 2);
                lrow[rh] = lrow[rh] * scale[rh] + lsum[rh];
            }
            #pragma unroll
            for (int an = 0; an < 8; an++) {
                o[an][0] *= scale[0]; o[an][1] *= scale[0];
                o[an][2] *= scale[1]; o[an][3] *= scale[1];
            }

            // stage P to smem (per-warp rows only), then PV MMA
            #pragma unroll
            for (int an = 0; an < 8; an++) {
                int col = an * 8 + 2 * l4;
                Ps[wr0 * PAD + col]           = s[an][0];
                Ps[wr0 * PAD + col + 1]       = s[an][1];
                Ps[(wr0 + 8) * PAD + col]     = s[an][2];
                Ps[(wr0 + 8) * PAD + col + 1] = s[an][3];
            }
            __syncwarp();
            #pragma unroll
            for (int ks = 0; ks < 8; ks++) {
                int kk = ks * 8 + l4;
                uint32_t ah[4], al[4];
                split_tf32(Ps[wr0 * PAD + kk],           ah[0], al[0]);
                split_tf32(Ps[(wr0 + 8) * PAD + kk],     ah[1], al[1]);
                split_tf32(Ps[wr0 * PAD + kk + 4],       ah[2], al[2]);
                split_tf32(Ps[(wr0 + 8) * PAD + kk + 4], ah[3], al[3]);
                #pragma unroll
                for (int an = 0; an < 8; an++) {
                    int nbv = an * 8 + g4;
                    uint32_t bh[2], bl[2];
                    split_tf32(Vs[kk * PAD + nbv],       bh[0], bl[0]);
                    split_tf32(Vs[(kk + 4) * PAD + nbv], bh[1], bl[1]);
                    mma8(o[an], ah, bh);
                    mma8(o[an], ah, bl);
                    mma8(o[an], al, bh);
                }
            }
            __syncwarp();
        } // j-tiles

        // normalize and store
        float inv0 = 1.f / lrow[0], inv1 = 1.f / lrow[1];
        #pragma unroll
        for (int an = 0; an < 8; an++) {
            int col = h * DH + an * 8 + 2 * l4;
            int r0 = i0 + wr0;
            if (wr0 < validRows) {
                av[(size_t)r0 * DM + col]     = o[an][0] * inv0;
                av[(size_t)r0 * DM + col + 1] = o[an][1] * inv0;
            }
            if (wr0 + 8 < validRows) {
                av[(size_t)(r0 + 8) * DM + col]     = o[an][2] * inv1;
                av[(size_t)(r0 + 8) * DM + col + 1] = o[an][3] * inv1;
            }
        }
    } // blocks
}

// ---------------- residual add + layernorm ----------------
__global__ void add_ln_kernel(float* __restrict__ w, const float* __restrict__ delta,
                              const float* __restrict__ gam, const float* __restrict__ bta) {
    int row = blockIdx.x;
    int tid = threadIdx.x;
    __shared__ float red[256];
    float x0 = w[row * DM + tid]       + delta[row * DM + tid];
    float x1 = w[row * DM + tid + 256] + delta[row * DM + tid + 256];
    red[tid] = x0 + x1; __syncthreads();
    for (int s = 128; s > 0; s >>= 1) {
        if (tid < s) red[tid] += red[tid + s];
        __syncthreads();
    }
    float mean = red[0] * (1.f / DM);
    __syncthreads();
    float d0 = x0 - mean, d1 = x1 - mean;
    red[tid] = d0 * d0 + d1 * d1; __syncthreads();
    for (int s = 128; s > 0; s >>= 1) {
        if (tid < s) red[tid] += red[tid + s];
        __syncthreads();
    }
    float inv = 1.f / sqrtf(red[0] * (1.f / DM) + 1e-5f);
    w[row * DM + tid]       = d0 * inv * gam[tid]       + bta[tid];
    w[row * DM + tid + 256] = d1 * inv * gam[tid + 256] + bta[tid + 256];
}

__global__ void copy_out_kernel(float* __restrict__ out) {
    int idx = blockIdx.x * blockDim.x + threadIdx.x;
    if (idx < TT * DM) out[idx] = g_w[idx];
}

// ---------------- launcher ----------------
extern "C" void kernel_launch(void* const* d_in, const int* in_sizes, int n_in,
                              void* d_out, int out_size) {
    (void)in_sizes; (void)n_in; (void)out_size;
    const float* word_emb = (const float*)d_in[0];
    const float* mem_tok  = (const float*)d_in[1];
    const float* Wqkv     = (const float*)d_in[2];
    const float* Wr       = (const float*)d_in[3];
    const float* Wo       = (const float*)d_in[4];
    const float* ln1s     = (const float*)d_in[5];
    const float* ln1b     = (const float*)d_in[6];
    const float* W1       = (const float*)d_in[7];
    const float* b1       = (const float*)d_in[8];
    const float* W2       = (const float*)d_in[9];
    const float* b2       = (const float*)d_in[10];
    const float* ln2s     = (const float*)d_in[11];
    const float* ln2b     = (const float*)d_in[12];
    const float* rwb      = (const float*)d_in[13];
    const float* rrb      = (const float*)d_in[14];

    float *g_w_p, *g_pos_p, *g_hd_p, *g_r_p, *g_av_p, *g_tmp_p, *g_ff1_p;
    cudaGetSymbolAddress((void**)&g_w_p,   g_w);
    cudaGetSymbolAddress((void**)&g_pos_p, g_pos);
    cudaGetSymbolAddress((void**)&g_hd_p,  g_heads);
    cudaGetSymbolAddress((void**)&g_r_p,   g_r);
    cudaGetSymbolAddress((void**)&g_av_p,  g_av);
    cudaGetSymbolAddress((void**)&g_tmp_p, g_tmp);
    cudaGetSymbolAddress((void**)&g_ff1_p, g_ff1);

    cudaFuncSetAttribute(fused_attn_kernel,
                         cudaFuncAttributeMaxDynamicSharedMemorySize, ATTN_SMEM);

    const int TD = TT * DM;
    build_w_kernel<<<(TD + 255) / 256, 256>>>(word_emb, mem_tok);
    build_pos_kernel<<<(TD + 255) / 256, 256>>>();

    const int MB = (TT + 127) / 128;   // 17

    for (int l = 0; l < NLAY; l++) {
        mma_gemm<<<dim3(3 * DM / 64, MB, 1), 256>>>(
            g_w_p, DM, Wqkv + (size_t)l * DM * 3 * DM, 3 * DM,
            g_hd_p, 3 * DM, nullptr, 0, TT, 3 * DM, DM);
        mma_gemm<<<dim3(DM / 64, MB, 1), 256>>>(
            g_pos_p, DM, Wr + (size_t)l * DM * DM, DM,
            g_r_p, DM, nullptr, 0, TT, DM, DM);

        fused_attn_kernel<<<dim3(NH, 17), 128, ATTN_SMEM>>>(
            g_hd_p, g_r_p, rwb, rrb, g_av_p);

        mma_gemm<<<dim3(DM / 64, MB, 1), 256>>>(
            g_av_p, DM, Wo + (size_t)l * DM * DM, DM,
            g_tmp_p, DM, nullptr, 0, TT, DM, DM);
        add_ln_kernel<<<TT, 256>>>(g_w_p, g_tmp_p, ln1s + l * DM, ln1b + l * DM);
        mma_gemm<<<dim3(DI / 64, MB, 1), 256>>>(
            g_w_p, DM, W1 + (size_t)l * DM * DI, DI,
            g_ff1_p, DI, b1 + (size_t)l * DI, 1, TT, DI, DM);
        mma_gemm<<<dim3(DM / 64, MB, 1), 256>>>(
            g_ff1_p, DI, W2 + (size_t)l * DI * DM, DM,
            g_tmp_p, DM, b2 + (size_t)l * DM, 0, TT, DM, DI);
        add_ln_kernel<<<TT, 256>>>(g_w_p, g_tmp_p, ln2s + l * DM, ln2b + l * DM);
    }

    copy_out_kernel<<<(TD + 255) / 256, 256>>>((float*)d_out);
}

// round 5
// speedup vs baseline: 1.4299x; 1.4299x over previous
#include <cuda_runtime.h>
#include <math.h>
#include <stdint.h>

// ---------------- problem constants ----------------
#define TT    2080
#define DM    512
#define NH    8
#define DH    64
#define DI    2048
#define NLAY  4
#define NMTOK 16
#define QL    2048

// ---------------- scratch ----------------
__device__ float g_w[TT * DM];
__device__ float g_pos[TT * DM];
__device__ float g_heads[TT * 3 * DM];
__device__ float g_r[TT * DM];
__device__ float g_av[TT * DM];
__device__ float g_tmp[TT * DM];
__device__ float g_ff1[TT * DI];

// ---------------- prep kernels ----------------
__global__ void build_w_kernel(const float* __restrict__ word_emb,
                               const float* __restrict__ mem) {
    int idx = blockIdx.x * blockDim.x + threadIdx.x;
    if (idx >= TT * DM) return;
    int row = idx / DM, c = idx % DM;
    float v;
    if (row < NMTOK)            v = mem[row * DM + c];
    else if (row < NMTOK + QL)  v = word_emb[(row - NMTOK) * DM + c];
    else                        v = mem[(row - NMTOK - QL) * DM + c];
    g_w[idx] = v;
}

__global__ void build_pos_kernel() {
    int idx = blockIdx.x * blockDim.x + threadIdx.x;
    if (idx >= TT * DM) return;
    int row = idx / DM, c = idx % DM;
    int f = (c < DM / 2) ? c : (c - DM / 2);
    double invf = exp(-((double)(2 * f) / (double)DM) * log(10000.0));
    double val = (double)(TT - 1 - row) * invf;
    g_pos[idx] = (float)((c < DM / 2) ? sin(val) : cos(val));
}

// ---------------- tf32 helpers ----------------
__device__ __forceinline__ void split_tf32(float x, uint32_t& hi, uint32_t& lo) {
    uint32_t h;
    asm("cvt.rna.tf32.f32 %0, %1;" : "=r"(h) : "f"(x));
    float r = x - __uint_as_float(h);
    uint32_t l;
    asm("cvt.rna.tf32.f32 %0, %1;" : "=r"(l) : "f"(r));
    hi = h; lo = l;
}

__device__ __forceinline__ void mma8(float (&c)[4], const uint32_t (&a)[4],
                                     const uint32_t (&b)[2]) {
    asm volatile(
        "mma.sync.aligned.m16n8k8.row.col.f32.tf32.tf32.f32 "
        "{%0,%1,%2,%3}, {%4,%5,%6,%7}, {%8,%9}, {%0,%1,%2,%3};"
        : "+f"(c[0]), "+f"(c[1]), "+f"(c[2]), "+f"(c[3])
        : "r"(a[0]), "r"(a[1]), "r"(a[2]), "r"(a[3]), "r"(b[0]), "r"(b[1]));
}

// ---------------- projection GEMM (3xTF32, NN) ----------------
#define LDA_S 36
#define LDB_NN 72

__global__ __launch_bounds__(256, 2)
void mma_gemm(const float* __restrict__ A, int lda,
              const float* __restrict__ B, int ldb,
              float* __restrict__ C, int ldc,
              const float* __restrict__ cbias, int doRelu,
              int M, int N, int K) {
    __shared__ float As[128 * LDA_S];
    __shared__ float Bs[32 * LDB_NN];

    const int bm = blockIdx.y * 128, bn = blockIdx.x * 64;
    const int tid = threadIdx.x;
    const int lane = tid & 31, warp = tid >> 5;
    const int wm = warp & 3, wn = warp >> 2;
    const int g4 = lane >> 2, l4 = lane & 3;

    float acc[2][4][4] = {};
    float4 pa[4], pb[2];

    auto loadA = [&](int k0) {
        const int r = tid >> 3, k4 = (tid & 7) * 4;
        #pragma unroll
        for (int p = 0; p < 4; p++) {
            int row = bm + p * 32 + r;
            float4 v = make_float4(0.f, 0.f, 0.f, 0.f);
            if (row < M) v = *reinterpret_cast<const float4*>(A + (size_t)row * lda + k0 + k4);
            pa[p] = v;
        }
    };
    auto loadB = [&](int k0) {
        const int r = tid >> 4, n4 = (tid & 15) * 4;
        #pragma unroll
        for (int p = 0; p < 2; p++) {
            int k = k0 + p * 16 + r;
            pb[p] = *reinterpret_cast<const float4*>(B + (size_t)k * ldb + bn + n4);
        }
    };
    auto storeAB = [&]() {
        {
            const int r = tid >> 3, k4 = (tid & 7) * 4;
            #pragma unroll
            for (int p = 0; p < 4; p++)
                *reinterpret_cast<float4*>(&As[(p * 32 + r) * LDA_S + k4]) = pa[p];
        }
        {
            const int r = tid >> 4, n4 = (tid & 15) * 4;
            #pragma unroll
            for (int p = 0; p < 2; p++)
                *reinterpret_cast<float4*>(&Bs[(p * 16 + r) * LDB_NN + n4]) = pb[p];
        }
    };

    loadA(0);
    loadB(0);

    for (int k0 = 0; k0 < K; k0 += 32) {
        storeAB();
        __syncthreads();
        if (k0 + 32 < K) { loadA(k0 + 32); loadB(k0 + 32); }

        #pragma unroll
        for (int ks = 0; ks < 4; ks++) {
            const int kk = ks * 8 + l4;
            uint32_t ah[2][4], al[2][4];
            #pragma unroll
            for (int am = 0; am < 2; am++) {
                int mb = wm * 32 + am * 16 + g4;
                split_tf32(As[mb * LDA_S + kk],           ah[am][0], al[am][0]);
                split_tf32(As[(mb + 8) * LDA_S + kk],     ah[am][1], al[am][1]);
                split_tf32(As[mb * LDA_S + kk + 4],       ah[am][2], al[am][2]);
                split_tf32(As[(mb + 8) * LDA_S + kk + 4], ah[am][3], al[am][3]);
            }
            uint32_t bh[4][2], bl[4][2];
            #pragma unroll
            for (int an = 0; an < 4; an++) {
                int nb = wn * 32 + an * 8 + g4;
                split_tf32(Bs[kk * LDB_NN + nb],       bh[an][0], bl[an][0]);
                split_tf32(Bs[(kk + 4) * LDB_NN + nb], bh[an][1], bl[an][1]);
            }
            #pragma unroll
            for (int am = 0; am < 2; am++)
                #pragma unroll
                for (int an = 0; an < 4; an++) {
                    mma8(acc[am][an], ah[am], bh[an]);
                    mma8(acc[am][an], ah[am], bl[an]);
                    mma8(acc[am][an], al[am], bh[an]);
                }
        }
        __syncthreads();
    }

    #pragma unroll
    for (int am = 0; am < 2; am++) {
        int row0 = bm + wm * 32 + am * 16 + g4;
        #pragma unroll
        for (int an = 0; an < 4; an++) {
            int col0 = bn + wn * 32 + an * 8 + 2 * l4;
            float v0 = acc[am][an][0], v1 = acc[am][an][1];
            float v2 = acc[am][an][2], v3 = acc[am][an][3];
            if (cbias) {
                float b0 = cbias[col0], b1 = cbias[col0 + 1];
                v0 += b0; v1 += b1; v2 += b0; v3 += b1;
            }
            if (doRelu) {
                v0 = fmaxf(v0, 0.f); v1 = fmaxf(v1, 0.f);
                v2 = fmaxf(v2, 0.f); v3 = fmaxf(v3, 0.f);
            }
            if (row0 < M) {
                C[(size_t)row0 * ldc + col0]     = v0;
                C[(size_t)row0 * ldc + col0 + 1] = v1;
            }
            if (row0 + 8 < M) {
                C[(size_t)(row0 + 8) * ldc + col0]     = v2;
                C[(size_t)(row0 + 8) * ldc + col0 + 1] = v3;
            }
        }
    }
}

// ---------------- fused flash-style relative attention v2 ----------------
// 256 threads = 8 warps (4 along M x 2 along N) per 64x64 tile.
// K/V/R tiles pre-split to tf32 hi/lo in smem at load time.
// BDraw rolling ring: 3 slots (live window is at most 3 consecutive chunks).
#define PAD 68
#define TS  (64 * PAD)
#define ATTN_SMEM ((12 * TS + 256) * 4)

__device__ __forceinline__ void split_store4(float4 v, uint32_t* hiP, uint32_t* loP) {
    uint4 hv, lv;
    split_tf32(v.x, hv.x, lv.x);
    split_tf32(v.y, hv.y, lv.y);
    split_tf32(v.z, hv.z, lv.z);
    split_tf32(v.w, hv.w, lv.w);
    *reinterpret_cast<uint4*>(hiP) = hv;
    *reinterpret_cast<uint4*>(loP) = lv;
}

__global__ __launch_bounds__(256, 1)
void fused_attn_kernel(const float* __restrict__ heads,
                       const float* __restrict__ rbuf,
                       const float* __restrict__ rwb,
                       const float* __restrict__ rrb,
                       float* __restrict__ av) {
    extern __shared__ float sm[];
    float*    Qw   = sm;
    float*    Qr   = sm + TS;
    uint32_t* Kh   = (uint32_t*)(sm + 2 * TS);
    uint32_t* Kl   = (uint32_t*)(sm + 3 * TS);
    uint32_t* Vh   = (uint32_t*)(sm + 4 * TS);
    uint32_t* Vl   = (uint32_t*)(sm + 5 * TS);
    uint32_t* Rh   = (uint32_t*)(sm + 6 * TS);
    uint32_t* Rl   = (uint32_t*)(sm + 7 * TS);
    float*    Ring = sm + 8 * TS;          // 3 slots
    float*    Ps   = sm + 11 * TS;
    float*    redm = sm + 12 * TS;         // [2][64]
    float*    reds = redm + 128;           // [2][64]

    const int h = blockIdx.x;
    const int p = blockIdx.y;
    const int tid = threadIdx.x;
    const int lane = tid & 31, warp = tid >> 5;
    const int wm = warp & 3, wn = warp >> 2;
    const int g4 = lane >> 2, l4 = lane & 3;
    const int wr0 = wm * 16 + g4;          // warp row base (+8 for second half)
    const int colbase = wn * 32;

    int blist[2]; int nblk;
    if (p < 16) { blist[0] = p; blist[1] = 31 - p; nblk = 2; }
    else        { blist[0] = 32; nblk = 1; }

    for (int bi = 0; bi < nblk; bi++) {
        const int b = blist[bi];
        const int i0 = b * 64;
        const int validRows = min(64, TT - i0);
        const int njt = (b < 32) ? (b + 1) : 33;

        __syncthreads();
        // Load Q (+ biases), fp32
        for (int t = tid; t < 64 * 16; t += 256) {
            int r = t >> 4, c4 = (t & 15) * 4;
            int grow = i0 + r;
            float4 q = make_float4(0.f, 0.f, 0.f, 0.f);
            if (grow < TT)
                q = *(const float4*)(heads + (size_t)grow * (3 * DM) + h * DH + c4);
            float4 bw = *(const float4*)(rwb + h * DH + c4);
            float4 br = *(const float4*)(rrb + h * DH + c4);
            *(float4*)(Qw + r * PAD + c4) =
                make_float4(q.x + bw.x, q.y + bw.y, q.z + bw.z, q.w + bw.w);
            *(float4*)(Qr + r * PAD + c4) =
                make_float4(q.x + br.x, q.y + br.y, q.z + br.z, q.w + br.w);
        }

        float o[4][4];
        #pragma unroll
        for (int a = 0; a < 4; a++) { o[a][0] = o[a][1] = o[a][2] = o[a][3] = 0.f; }
        float mrow[2] = {-1e30f, -1e30f};
        float lrow[2] = {0.f, 0.f};

        int nextChunk = (2016 - i0) / 64;
        if (nextChunk < 0) nextChunk = 0;

        for (int jt = 0; jt < njt; jt++) {
            const int j0 = jt * 64;

            // ---- build any new BDraw chunks needed ----
            const int hiJr = min(TT - 1, TT - 1 - i0 + j0 + 63);
            const int chi = hiJr >> 6;
            while (nextChunk <= chi) {
                const int c = nextChunk;
                __syncthreads();
                for (int t = tid; t < 64 * 16; t += 256) {
                    int r = t >> 4, c4 = (t & 15) * 4;
                    int grow = c * 64 + r;
                    float4 v = make_float4(0.f, 0.f, 0.f, 0.f);
                    if (grow < TT)
                        v = *(const float4*)(rbuf + (size_t)grow * DM + h * DH + c4);
                    split_store4(v, Rh + r * PAD + c4, Rl + r * PAD + c4);
                }
                __syncthreads();
                float cacc[4][4];
                #pragma unroll
                for (int a = 0; a < 4; a++)
                    cacc[a][0] = cacc[a][1] = cacc[a][2] = cacc[a][3] = 0.f;
                #pragma unroll
                for (int ks = 0; ks < 8; ks++) {
                    int kk = ks * 8 + l4;
                    uint32_t ah[4], al[4];
                    split_tf32(Qr[wr0 * PAD + kk],           ah[0], al[0]);
                    split_tf32(Qr[(wr0 + 8) * PAD + kk],     ah[1], al[1]);
                    split_tf32(Qr[wr0 * PAD + kk + 4],       ah[2], al[2]);
                    split_tf32(Qr[(wr0 + 8) * PAD + kk + 4], ah[3], al[3]);
                    #pragma unroll
                    for (int an = 0; an < 4; an++) {
                        int nb = colbase + an * 8 + g4;
                        uint32_t bh[2] = {Rh[nb * PAD + kk], Rh[nb * PAD + kk + 4]};
                        uint32_t bl[2] = {Rl[nb * PAD + kk], Rl[nb * PAD + kk + 4]};
                        mma8(cacc[an], ah, bh);
                        mma8(cacc[an], ah, bl);
                        mma8(cacc[an], al, bh);
                    }
                }
                float* slot = Ring + (c % 3) * TS;
                #pragma unroll
                for (int an = 0; an < 4; an++) {
                    int col = colbase + an * 8 + 2 * l4;
                    slot[wr0 * PAD + col]           = cacc[an][0];
                    slot[wr0 * PAD + col + 1]       = cacc[an][1];
                    slot[(wr0 + 8) * PAD + col]     = cacc[an][2];
                    slot[(wr0 + 8) * PAD + col + 1] = cacc[an][3];
                }
                nextChunk++;
            }

            // ---- load K/V tile (pre-split) ----
            __syncthreads();
            for (int t = tid; t < 64 * 16; t += 256) {
                int r = t >> 4, c4 = (t & 15) * 4;
                int grow = j0 + r;
                float4 kv = make_float4(0.f, 0.f, 0.f, 0.f), vv = kv;
                if (grow < TT) {
                    kv = *(const float4*)(heads + (size_t)grow * (3 * DM) + DM + h * DH + c4);
                    vv = *(const float4*)(heads + (size_t)grow * (3 * DM) + 2 * DM + h * DH + c4);
                }
                split_store4(kv, Kh + r * PAD + c4, Kl + r * PAD + c4);
                split_store4(vv, Vh + r * PAD + c4, Vl + r * PAD + c4);
            }
            __syncthreads();

            // ---- AC MMA ----
            float s[4][4];
            #pragma unroll
            for (int a = 0; a < 4; a++)
                s[a][0] = s[a][1] = s[a][2] = s[a][3] = 0.f;
            #pragma unroll
            for (int ks = 0; ks < 8; ks++) {
                int kk = ks * 8 + l4;
                uint32_t ah[4], al[4];
                split_tf32(Qw[wr0 * PAD + kk],           ah[0], al[0]);
                split_tf32(Qw[(wr0 + 8) * PAD + kk],     ah[1], al[1]);
                split_tf32(Qw[wr0 * PAD + kk + 4],       ah[2], al[2]);
                split_tf32(Qw[(wr0 + 8) * PAD + kk + 4], ah[3], al[3]);
                #pragma unroll
                for (int an = 0; an < 4; an++) {
                    int nb = colbase + an * 8 + g4;
                    uint32_t bh[2] = {Kh[nb * PAD + kk], Kh[nb * PAD + kk + 4]};
                    uint32_t bl[2] = {Kl[nb * PAD + kk], Kl[nb * PAD + kk + 4]};
                    mma8(s[an], ah, bh);
                    mma8(s[an], ah, bl);
                    mma8(s[an], al, bh);
                }
            }

            // ---- combine with rel-shifted BD + mask + scale ----
            float tmax[2] = {-1e30f, -1e30f};
            #pragma unroll
            for (int an = 0; an < 4; an++) {
                #pragma unroll
                for (int e = 0; e < 4; e++) {
                    int rh = e >> 1;
                    int di = wr0 + rh * 8;
                    int dj = colbase + an * 8 + 2 * l4 + (e & 1);
                    int i = i0 + di, j = j0 + dj;
                    float v = -1e30f;
                    if (di < validRows && j < TT) {
                        int jmaxr = (i < NMTOK) ? (NMTOK - 1)
                                  : ((i >= TT - NMTOK) ? (TT - 1) : i);
                        if (j <= jmaxr) {
                            float bd;
                            if (j <= i) {
                                int jr = TT - 1 - i + j;
                                bd = Ring[((jr >> 6) % 3) * TS + di * PAD + (jr & 63)];
                            } else if (j == i + 1) {
                                bd = 0.f;
                            } else {
                                const float* qrow = Qr + (di + 1) * PAD;
                                const float* rr = rbuf + (size_t)(j - i - 2) * DM + h * DH;
                                float accd = 0.f;
                                #pragma unroll 8
                                for (int d = 0; d < DH; d++) accd += qrow[d] * rr[d];
                                bd = accd;
                            }
                            v = (s[an][e] + bd) * 0.125f;
                        }
                    }
                    s[an][e] = v;
                    tmax[rh] = fmaxf(tmax[rh], v);
                }
            }
            #pragma unroll
            for (int rh = 0; rh < 2; rh++) {
                tmax[rh] = fmaxf(tmax[rh], __shfl_xor_sync(0xffffffffu, tmax[rh], 1));
                tmax[rh] = fmaxf(tmax[rh], __shfl_xor_sync(0xffffffffu, tmax[rh], 2));
            }
            if (l4 == 0) {
                redm[wn * 64 + wm * 16 + g4]     = tmax[0];
                redm[wn * 64 + wm * 16 + g4 + 8] = tmax[1];
            }
            __syncthreads();

            float scl[2], lsum[2] = {0.f, 0.f};
            #pragma unroll
            for (int rh = 0; rh < 2; rh++) {
                int row = wm * 16 + g4 + rh * 8;
                float tm = fmaxf(redm[row], redm[64 + row]);
                float mnew = fmaxf(mrow[rh], tm);
                scl[rh] = expf(mrow[rh] - mnew);
                mrow[rh] = mnew;
            }
            #pragma unroll
            for (int an = 0; an < 4; an++) {
                #pragma unroll
                for (int e = 0; e < 4; e++) {
                    int rh = e >> 1;
                    float ev = expf(s[an][e] - mrow[rh]);
                    s[an][e] = ev;
                    lsum[rh] += ev;
                }
            }
            #pragma unroll
            for (int rh = 0; rh < 2; rh++) {
                lsum[rh] += __shfl_xor_sync(0xffffffffu, lsum[rh], 1);
                lsum[rh] += __shfl_xor_sync(0xffffffffu, lsum[rh], 2);
            }
            if (l4 == 0) {
                reds[wn * 64 + wm * 16 + g4]     = lsum[0];
                reds[wn * 64 + wm * 16 + g4 + 8] = lsum[1];
            }
            // stage P to smem
            #pragma unroll
            for (int an = 0; an < 4; an++) {
                int col = colbase + an * 8 + 2 * l4;
                Ps[wr0 * PAD + col]           = s[an][0];
                Ps[wr0 * PAD + col + 1]       = s[an][1];
                Ps[(wr0 + 8) * PAD + col]     = s[an][2];
                Ps[(wr0 + 8) * PAD + col + 1] = s[an][3];
            }
            __syncthreads();

            #pragma unroll
            for (int rh = 0; rh < 2; rh++) {
                int row = wm * 16 + g4 + rh * 8;
                lrow[rh] = lrow[rh] * scl[rh] + reds[row] + reds[64 + row];
            }
            #pragma unroll
            for (int an = 0; an < 4; an++) {
                o[an][0] *= scl[0]; o[an][1] *= scl[0];
                o[an][2] *= scl[1]; o[an][3] *= scl[1];
            }

            // ---- PV MMA (P from smem, split in-loop; V pre-split) ----
            #pragma unroll
            for (int ks = 0; ks < 8; ks++) {
                int kk = ks * 8 + l4;
                uint32_t ah[4], al[4];
                split_tf32(Ps[wr0 * PAD + kk],           ah[0], al[0]);
                split_tf32(Ps[(wr0 + 8) * PAD + kk],     ah[1], al[1]);
                split_tf32(Ps[wr0 * PAD + kk + 4],       ah[2], al[2]);
                split_tf32(Ps[(wr0 + 8) * PAD + kk + 4], ah[3], al[3]);
                #pragma unroll
                for (int an = 0; an < 4; an++) {
                    int nbv = colbase + an * 8 + g4;
                    uint32_t bh[2] = {Vh[kk * PAD + nbv], Vh[(kk + 4) * PAD + nbv]};
                    uint32_t bl[2] = {Vl[kk * PAD + nbv], Vl[(kk + 4) * PAD + nbv]};
                    mma8(o[an], ah, bh);
                    mma8(o[an], ah, bl);
                    mma8(o[an], al, bh);
                }
            }
        } // j-tiles

        // normalize and store
        float inv0 = 1.f / lrow[0], inv1 = 1.f / lrow[1];
        #pragma unroll
        for (int an = 0; an < 4; an++) {
            int col = h * DH + colbase + an * 8 + 2 * l4;
            int r0 = i0 + wr0;
            if (wr0 < validRows) {
                av[(size_t)r0 * DM + col]     = o[an][0] * inv0;
                av[(size_t)r0 * DM + col + 1] = o[an][1] * inv0;
            }
            if (wr0 + 8 < validRows) {
                av[(size_t)(r0 + 8) * DM + col]     = o[an][2] * inv1;
                av[(size_t)(r0 + 8) * DM + col + 1] = o[an][3] * inv1;
            }
        }
    } // blocks
}

// ---------------- residual add + layernorm ----------------
__global__ void add_ln_kernel(float* __restrict__ w, const float* __restrict__ delta,
                              const float* __restrict__ gam, const float* __restrict__ bta) {
    int row = blockIdx.x;
    int tid = threadIdx.x;
    __shared__ float red[256];
    float x0 = w[row * DM + tid]       + delta[row * DM + tid];
    float x1 = w[row * DM + tid + 256] + delta[row * DM + tid + 256];
    red[tid] = x0 + x1; __syncthreads();
    for (int s = 128; s > 0; s >>= 1) {
        if (tid < s) red[tid] += red[tid + s];
        __syncthreads();
    }
    float mean = red[0] * (1.f / DM);
    __syncthreads();
    float d0 = x0 - mean, d1 = x1 - mean;
    red[tid] = d0 * d0 + d1 * d1; __syncthreads();
    for (int s = 128; s > 0; s >>= 1) {
        if (tid < s) red[tid] += red[tid + s];
        __syncthreads();
    }
    float inv = 1.f / sqrtf(red[0] * (1.f / DM) + 1e-5f);
    w[row * DM + tid]       = d0 * inv * gam[tid]       + bta[tid];
    w[row * DM + tid + 256] = d1 * inv * gam[tid + 256] + bta[tid + 256];
}

__global__ void copy_out_kernel(float* __restrict__ out) {
    int idx = blockIdx.x * blockDim.x + threadIdx.x;
    if (idx < TT * DM) out[idx] = g_w[idx];
}

// ---------------- launcher ----------------
extern "C" void kernel_launch(void* const* d_in, const int* in_sizes, int n_in,
                              void* d_out, int out_size) {
    (void)in_sizes; (void)n_in; (void)out_size;
    const float* word_emb = (const float*)d_in[0];
    const float* mem_tok  = (const float*)d_in[1];
    const float* Wqkv     = (const float*)d_in[2];
    const float* Wr       = (const float*)d_in[3];
    const float* Wo       = (const float*)d_in[4];
    const float* ln1s     = (const float*)d_in[5];
    const float* ln1b     = (const float*)d_in[6];
    const float* W1       = (const float*)d_in[7];
    const float* b1       = (const float*)d_in[8];
    const float* W2       = (const float*)d_in[9];
    const float* b2       = (const float*)d_in[10];
    const float* ln2s     = (const float*)d_in[11];
    const float* ln2b     = (const float*)d_in[12];
    const float* rwb      = (const float*)d_in[13];
    const float* rrb      = (const float*)d_in[14];

    float *g_w_p, *g_pos_p, *g_hd_p, *g_r_p, *g_av_p, *g_tmp_p, *g_ff1_p;
    cudaGetSymbolAddress((void**)&g_w_p,   g_w);
    cudaGetSymbolAddress((void**)&g_pos_p, g_pos);
    cudaGetSymbolAddress((void**)&g_hd_p,  g_heads);
    cudaGetSymbolAddress((void**)&g_r_p,   g_r);
    cudaGetSymbolAddress((void**)&g_av_p,  g_av);
    cudaGetSymbolAddress((void**)&g_tmp_p, g_tmp);
    cudaGetSymbolAddress((void**)&g_ff1_p, g_ff1);

    cudaFuncSetAttribute(fused_attn_kernel,
                         cudaFuncAttributeMaxDynamicSharedMemorySize, ATTN_SMEM);

    const int TD = TT * DM;
    build_w_kernel<<<(TD + 255) / 256, 256>>>(word_emb, mem_tok);
    build_pos_kernel<<<(TD + 255) / 256, 256>>>();

    const int MB = (TT + 127) / 128;   // 17

    for (int l = 0; l < NLAY; l++) {
        mma_gemm<<<dim3(3 * DM / 64, MB, 1), 256>>>(
            g_w_p, DM, Wqkv + (size_t)l * DM * 3 * DM, 3 * DM,
            g_hd_p, 3 * DM, nullptr, 0, TT, 3 * DM, DM);
        mma_gemm<<<dim3(DM / 64, MB, 1), 256>>>(
            g_pos_p, DM, Wr + (size_t)l * DM * DM, DM,
            g_r_p, DM, nullptr, 0, TT, DM, DM);

        fused_attn_kernel<<<dim3(NH, 17), 256, ATTN_SMEM>>>(
            g_hd_p, g_r_p, rwb, rrb, g_av_p);

        mma_gemm<<<dim3(DM / 64, MB, 1), 256>>>(
            g_av_p, DM, Wo + (size_t)l * DM * DM, DM,
            g_tmp_p, DM, nullptr, 0, TT, DM, DM);
        add_ln_kernel<<<TT, 256>>>(g_w_p, g_tmp_p, ln1s + l * DM, ln1b + l * DM);
        mma_gemm<<<dim3(DI / 64, MB, 1), 256>>>(
            g_w_p, DM, W1 + (size_t)l * DM * DI, DI,
            g_ff1_p, DI, b1 + (size_t)l * DI, 1, TT, DI, DM);
        mma_gemm<<<dim3(DM / 64, MB, 1), 256>>>(
            g_ff1_p, DI, W2 + (size_t)l * DI * DM, DM,
            g_tmp_p, DM, b2 + (size_t)l * DM, 0, TT, DM, DI);
        add_ln_kernel<<<TT, 256>>>(g_w_p, g_tmp_p, ln2s + l * DM, ln2b + l * DM);
    }

    copy_out_kernel<<<(TD + 255) / 256, 256>>>((float*)d_out);
}

// round 6
// speedup vs baseline: 1.6345x; 1.1431x over previous
#include <cuda_runtime.h>
#include <cuda_bf16.h>
#include <math.h>
#include <stdint.h>

// ---------------- problem constants ----------------
#define TT    2080
#define DM    512
#define NH    8
#define DH    64
#define DI    2048
#define NLAY  4
#define NMTOK 16
#define QL    2048

// ---------------- scratch ----------------
__device__ float g_w[TT * DM];
__device__ float g_pos[TT * DM];
__device__ float g_heads[TT * 3 * DM];
__device__ float g_r[TT * DM];
__device__ float g_av[TT * DM];
__device__ float g_tmp[TT * DM];
__device__ float g_ff1[TT * DI];

// ---------------- prep kernels ----------------
__global__ void build_w_kernel(const float* __restrict__ word_emb,
                               const float* __restrict__ mem) {
    int idx = blockIdx.x * blockDim.x + threadIdx.x;
    if (idx >= TT * DM) return;
    int row = idx / DM, c = idx % DM;
    float v;
    if (row < NMTOK)            v = mem[row * DM + c];
    else if (row < NMTOK + QL)  v = word_emb[(row - NMTOK) * DM + c];
    else                        v = mem[(row - NMTOK - QL) * DM + c];
    g_w[idx] = v;
}

__global__ void build_pos_kernel() {
    int idx = blockIdx.x * blockDim.x + threadIdx.x;
    if (idx >= TT * DM) return;
    int row = idx / DM, c = idx % DM;
    int f = (c < DM / 2) ? c : (c - DM / 2);
    double invf = exp(-((double)(2 * f) / (double)DM) * log(10000.0));
    double val = (double)(TT - 1 - row) * invf;
    g_pos[idx] = (float)((c < DM / 2) ? sin(val) : cos(val));
}

// ---------------- bf16x3 helpers ----------------
// pack (x0 -> low half / even k, x1 -> high half / odd k), hi plane + residual plane
__device__ __forceinline__ void split2(float x0, float x1, uint32_t& hw, uint32_t& lw) {
    __nv_bfloat162 h, l;
    h.x = __float2bfloat16(x0);
    h.y = __float2bfloat16(x1);
    l.x = __float2bfloat16(x0 - __bfloat162float(h.x));
    l.y = __float2bfloat16(x1 - __bfloat162float(h.y));
    hw = *reinterpret_cast<uint32_t*>(&h);
    lw = *reinterpret_cast<uint32_t*>(&l);
}

__device__ __forceinline__ void mma16(float (&c)[4], const uint32_t (&a)[4],
                                      const uint32_t (&b)[2]) {
    asm volatile(
        "mma.sync.aligned.m16n8k16.row.col.f32.bf16.bf16.f32 "
        "{%0,%1,%2,%3}, {%4,%5,%6,%7}, {%8,%9}, {%0,%1,%2,%3};"
        : "+f"(c[0]), "+f"(c[1]), "+f"(c[2]), "+f"(c[3])
        : "r"(a[0]), "r"(a[1]), "r"(a[2]), "r"(a[3]), "r"(b[0]), "r"(b[1]));
}

// ---------------- projection GEMM (bf16x3, NN) ----------------
// Block 128x64, BK=32, 8 warps (4M x 2N), warp tile 32x32 (2 m-atoms x 4 n-atoms m16n8k16).
#define PPA 20   // A plane row stride (words; 16 pairs used)
#define PPB 33   // B plane row stride (words; 16 pairs used)

__global__ __launch_bounds__(256, 2)
void mma_gemm(const float* __restrict__ A, int lda,
              const float* __restrict__ B, int ldb,
              float* __restrict__ C, int ldc,
              const float* __restrict__ cbias, int doRelu,
              int M, int N, int K) {
    __shared__ uint32_t Ah[128 * PPA], Al[128 * PPA];
    __shared__ uint32_t Bh[64 * PPB],  Bl[64 * PPB];

    const int bm = blockIdx.y * 128, bn = blockIdx.x * 64;
    const int tid = threadIdx.x;
    const int lane = tid & 31, warp = tid >> 5;
    const int wm = warp & 3, wn = warp >> 2;
    const int g4 = lane >> 2, l4 = lane & 3;

    float acc[2][4][4] = {};
    float4 pa[4], pb[2];

    const int ar = tid >> 3, ak4 = (tid & 7) * 4;      // A load coords
    const int bkp = tid >> 4, bn4 = (tid & 15) * 4;    // B load coords (key-pair)

    auto loadA = [&](int k0) {
        #pragma unroll
        for (int p = 0; p < 4; p++) {
            int row = bm + p * 32 + ar;
            float4 v = make_float4(0.f, 0.f, 0.f, 0.f);
            if (row < M) v = *reinterpret_cast<const float4*>(A + (size_t)row * lda + k0 + ak4);
            pa[p] = v;
        }
    };
    auto loadB = [&](int k0) {
        pb[0] = *reinterpret_cast<const float4*>(B + (size_t)(k0 + 2 * bkp) * ldb + bn + bn4);
        pb[1] = *reinterpret_cast<const float4*>(B + (size_t)(k0 + 2 * bkp + 1) * ldb + bn + bn4);
    };
    auto storeAB = [&]() {
        #pragma unroll
        for (int p = 0; p < 4; p++) {
            int row = p * 32 + ar;
            uint32_t h0, l0, h1, l1;
            split2(pa[p].x, pa[p].y, h0, l0);
            split2(pa[p].z, pa[p].w, h1, l1);
            int wi = row * PPA + (ak4 >> 1);
            Ah[wi] = h0; Ah[wi + 1] = h1;
            Al[wi] = l0; Al[wi + 1] = l1;
        }
        const float* p0 = &pb[0].x;
        const float* p1 = &pb[1].x;
        #pragma unroll
        for (int i = 0; i < 4; i++) {
            uint32_t hw, lw;
            split2(p0[i], p1[i], hw, lw);   // low = even k
            int wi = (bn4 + i) * PPB + bkp;
            Bh[wi] = hw; Bl[wi] = lw;
        }
    };

    loadA(0);
    loadB(0);

    for (int k0 = 0; k0 < K; k0 += 32) {
        storeAB();
        __syncthreads();
        if (k0 + 32 < K) { loadA(k0 + 32); loadB(k0 + 32); }

        #pragma unroll
        for (int ks = 0; ks < 2; ks++) {
            const int kc2 = ks * 8;
            uint32_t ah[2][4], al[2][4];
            #pragma unroll
            for (int am = 0; am < 2; am++) {
                int m = wm * 32 + am * 16 + g4;
                ah[am][0] = Ah[m * PPA + kc2 + l4];
                ah[am][1] = Ah[(m + 8) * PPA + kc2 + l4];
                ah[am][2] = Ah[m * PPA + kc2 + l4 + 4];
                ah[am][3] = Ah[(m + 8) * PPA + kc2 + l4 + 4];
                al[am][0] = Al[m * PPA + kc2 + l4];
                al[am][1] = Al[(m + 8) * PPA + kc2 + l4];
                al[am][2] = Al[m * PPA + kc2 + l4 + 4];
                al[am][3] = Al[(m + 8) * PPA + kc2 + l4 + 4];
            }
            uint32_t bh[4][2], bl[4][2];
            #pragma unroll
            for (int an = 0; an < 4; an++) {
                int n = wn * 32 + an * 8 + g4;
                bh[an][0] = Bh[n * PPB + kc2 + l4];
                bh[an][1] = Bh[n * PPB + kc2 + l4 + 4];
                bl[an][0] = Bl[n * PPB + kc2 + l4];
                bl[an][1] = Bl[n * PPB + kc2 + l4 + 4];
            }
            #pragma unroll
            for (int am = 0; am < 2; am++)
                #pragma unroll
                for (int an = 0; an < 4; an++) {
                    mma16(acc[am][an], ah[am], bh[an]);
                    mma16(acc[am][an], ah[am], bl[an]);
                    mma16(acc[am][an], al[am], bh[an]);
                }
        }
        __syncthreads();
    }

    #pragma unroll
    for (int am = 0; am < 2; am++) {
        int row0 = bm + wm * 32 + am * 16 + g4;
        #pragma unroll
        for (int an = 0; an < 4; an++) {
            int col0 = bn + wn * 32 + an * 8 + 2 * l4;
            float v0 = acc[am][an][0], v1 = acc[am][an][1];
            float v2 = acc[am][an][2], v3 = acc[am][an][3];
            if (cbias) {
                float b0 = cbias[col0], b1 = cbias[col0 + 1];
                v0 += b0; v1 += b1; v2 += b0; v3 += b1;
            }
            if (doRelu) {
                v0 = fmaxf(v0, 0.f); v1 = fmaxf(v1, 0.f);
                v2 = fmaxf(v2, 0.f); v3 = fmaxf(v3, 0.f);
            }
            if (row0 < M) {
                C[(size_t)row0 * ldc + col0]     = v0;
                C[(size_t)row0 * ldc + col0 + 1] = v1;
            }
            if (row0 + 8 < M) {
                C[(size_t)(row0 + 8) * ldc + col0]     = v2;
                C[(size_t)(row0 + 8) * ldc + col0 + 1] = v3;
            }
        }
    }
}

// ---------------- fused flash-style relative attention (bf16x3) ----------------
#define SQ 36          // stride (words) for Q/K/R/P pair planes [64][SQ]
#define SV 33          // stride for transposed V planes [64][SV]
#define RPAD 68        // ring fp32 row stride
#define RSLOT (64 * RPAD)
// words: 8*64*SQ + 2*64*SV + 2*64*SQ + 3*RSLOT + 256
#define ATTN_WORDS (10 * 64 * SQ + 2 * 64 * SV + 3 * RSLOT + 256)
#define ATTN_SMEM (ATTN_WORDS * 4)

__global__ __launch_bounds__(256, 1)
void fused_attn_kernel(const float* __restrict__ heads,
                       const float* __restrict__ rbuf,
                       const float* __restrict__ rwb,
                       const float* __restrict__ rrb,
                       float* __restrict__ av) {
    extern __shared__ uint32_t smu[];
    uint32_t* Qwh = smu;
    uint32_t* Qwl = Qwh + 64 * SQ;
    uint32_t* Qrh = Qwl + 64 * SQ;
    uint32_t* Qrl = Qrh + 64 * SQ;
    uint32_t* Kh  = Qrl + 64 * SQ;
    uint32_t* Kl  = Kh  + 64 * SQ;
    uint32_t* Rh  = Kl  + 64 * SQ;
    uint32_t* Rl  = Rh  + 64 * SQ;
    uint32_t* Vth = Rl  + 64 * SQ;
    uint32_t* Vtl = Vth + 64 * SV;
    uint32_t* Ph  = Vtl + 64 * SV;
    uint32_t* Pl  = Ph  + 64 * SQ;
    float* Ring = (float*)(Pl + 64 * SQ);
    float* redm = Ring + 3 * RSLOT;
    float* reds = redm + 128;

    const int h = blockIdx.x;
    const int p = blockIdx.y;
    const int tid = threadIdx.x;
    const int lane = tid & 31, warp = tid >> 5;
    const int wm = warp & 3, wn = warp >> 2;
    const int g4 = lane >> 2, l4 = lane & 3;
    const int wr0 = wm * 16 + g4;
    const int colbase = wn * 32;

    int blist[2]; int nblk;
    if (p < 16) { blist[0] = p; blist[1] = 31 - p; nblk = 2; }
    else        { blist[0] = 32; nblk = 1; }

    for (int bi = 0; bi < nblk; bi++) {
        const int b = blist[bi];
        const int i0 = b * 64;
        const int validRows = min(64, TT - i0);
        const int njt = (b < 32) ? (b + 1) : 33;

        __syncthreads();
        // Load Q (+ biases), pre-split into pair planes
        for (int t = tid; t < 64 * 16; t += 256) {
            int r = t >> 4, c4 = (t & 15) * 4;
            int grow = i0 + r;
            float4 q = make_float4(0.f, 0.f, 0.f, 0.f);
            if (grow < TT)
                q = *(const float4*)(heads + (size_t)grow * (3 * DM) + h * DH + c4);
            float4 bw = *(const float4*)(rwb + h * DH + c4);
            float4 br = *(const float4*)(rrb + h * DH + c4);
            int wi = r * SQ + (c4 >> 1);
            uint32_t hw, lw;
            split2(q.x + bw.x, q.y + bw.y, hw, lw); Qwh[wi] = hw;     Qwl[wi] = lw;
            split2(q.z + bw.z, q.w + bw.w, hw, lw); Qwh[wi + 1] = hw; Qwl[wi + 1] = lw;
            split2(q.x + br.x, q.y + br.y, hw, lw); Qrh[wi] = hw;     Qrl[wi] = lw;
            split2(q.z + br.z, q.w + br.w, hw, lw); Qrh[wi + 1] = hw; Qrl[wi + 1] = lw;
        }

        float o[4][4];
        #pragma unroll
        for (int a = 0; a < 4; a++) { o[a][0] = o[a][1] = o[a][2] = o[a][3] = 0.f; }
        float mrow[2] = {-1e30f, -1e30f};
        float lrow[2] = {0.f, 0.f};

        int nextChunk = (2016 - i0) / 64;
        if (nextChunk < 0) nextChunk = 0;

        for (int jt = 0; jt < njt; jt++) {
            const int j0 = jt * 64;

            // ---- build BDraw chunks ----
            const int hiJr = min(TT - 1, TT - 1 - i0 + j0 + 63);
            const int chi = hiJr >> 6;
            while (nextChunk <= chi) {
                const int c = nextChunk;
                __syncthreads();
                for (int t = tid; t < 64 * 16; t += 256) {
                    int r = t >> 4, c4 = (t & 15) * 4;
                    int grow = c * 64 + r;
                    float4 v = make_float4(0.f, 0.f, 0.f, 0.f);
                    if (grow < TT)
                        v = *(const float4*)(rbuf + (size_t)grow * DM + h * DH + c4);
                    int wi = r * SQ + (c4 >> 1);
                    uint32_t hw, lw;
                    split2(v.x, v.y, hw, lw); Rh[wi] = hw;     Rl[wi] = lw;
                    split2(v.z, v.w, hw, lw); Rh[wi + 1] = hw; Rl[wi + 1] = lw;
                }
                __syncthreads();
                float cacc[4][4];
                #pragma unroll
                for (int a = 0; a < 4; a++)
                    cacc[a][0] = cacc[a][1] = cacc[a][2] = cacc[a][3] = 0.f;
                #pragma unroll
                for (int kc = 0; kc < 4; kc++) {
                    const int kc2 = kc * 8;
                    uint32_t ah[4], al[4];
                    ah[0] = Qrh[wr0 * SQ + kc2 + l4];
                    ah[1] = Qrh[(wr0 + 8) * SQ + kc2 + l4];
                    ah[2] = Qrh[wr0 * SQ + kc2 + l4 + 4];
                    ah[3] = Qrh[(wr0 + 8) * SQ + kc2 + l4 + 4];
                    al[0] = Qrl[wr0 * SQ + kc2 + l4];
                    al[1] = Qrl[(wr0 + 8) * SQ + kc2 + l4];
                    al[2] = Qrl[wr0 * SQ + kc2 + l4 + 4];
                    al[3] = Qrl[(wr0 + 8) * SQ + kc2 + l4 + 4];
                    #pragma unroll
                    for (int an = 0; an < 4; an++) {
                        int n = colbase + an * 8 + g4;
                        uint32_t bh[2] = {Rh[n * SQ + kc2 + l4], Rh[n * SQ + kc2 + l4 + 4]};
                        uint32_t bl[2] = {Rl[n * SQ + kc2 + l4], Rl[n * SQ + kc2 + l4 + 4]};
                        mma16(cacc[an], ah, bh);
                        mma16(cacc[an], ah, bl);
                        mma16(cacc[an], al, bh);
                    }
                }
                float* slot = Ring + (c % 3) * RSLOT;
                #pragma unroll
                for (int an = 0; an < 4; an++) {
                    int col = colbase + an * 8 + 2 * l4;
                    slot[wr0 * RPAD + col]           = cacc[an][0];
                    slot[wr0 * RPAD + col + 1]       = cacc[an][1];
                    slot[(wr0 + 8) * RPAD + col]     = cacc[an][2];
                    slot[(wr0 + 8) * RPAD + col + 1] = cacc[an][3];
                }
                nextChunk++;
            }

            // ---- load K tile (pair planes) + V tile (transposed pair planes) ----
            __syncthreads();
            for (int t = tid; t < 64 * 16; t += 256) {
                int r = t >> 4, c4 = (t & 15) * 4;
                int grow = j0 + r;
                float4 kv = make_float4(0.f, 0.f, 0.f, 0.f);
                if (grow < TT)
                    kv = *(const float4*)(heads + (size_t)grow * (3 * DM) + DM + h * DH + c4);
                int wi = r * SQ + (c4 >> 1);
                uint32_t hw, lw;
                split2(kv.x, kv.y, hw, lw); Kh[wi] = hw;     Kl[wi] = lw;
                split2(kv.z, kv.w, hw, lw); Kh[wi + 1] = hw; Kl[wi + 1] = lw;
            }
            {   // V transpose: thread owns key-pair kp, 8 features
                int kp = tid >> 3, fb = (tid & 7) * 8;
                int jA = j0 + 2 * kp, jB = jA + 1;
                float4 a0 = make_float4(0.f, 0.f, 0.f, 0.f), a1 = a0, b0 = a0, b1 = a0;
                if (jA < TT) {
                    a0 = *(const float4*)(heads + (size_t)jA * (3 * DM) + 2 * DM + h * DH + fb);
                    a1 = *(const float4*)(heads + (size_t)jA * (3 * DM) + 2 * DM + h * DH + fb + 4);
                }
                if (jB < TT) {
                    b0 = *(const float4*)(heads + (size_t)jB * (3 * DM) + 2 * DM + h * DH + fb);
                    b1 = *(const float4*)(heads + (size_t)jB * (3 * DM) + 2 * DM + h * DH + fb + 4);
                }
                const float* pa0 = &a0.x; const float* pa1 = &a1.x;
                const float* pb0 = &b0.x; const float* pb1 = &b1.x;
                #pragma unroll
                for (int i = 0; i < 4; i++) {
                    uint32_t hw, lw;
                    split2(pa0[i], pb0[i], hw, lw);           // low = even key
                    Vth[(fb + i) * SV + kp] = hw; Vtl[(fb + i) * SV + kp] = lw;
                    split2(pa1[i], pb1[i], hw, lw);
                    Vth[(fb + 4 + i) * SV + kp] = hw; Vtl[(fb + 4 + i) * SV + kp] = lw;
                }
            }
            __syncthreads();

            // ---- AC MMA ----
            float s[4][4];
            #pragma unroll
            for (int a = 0; a < 4; a++)
                s[a][0] = s[a][1] = s[a][2] = s[a][3] = 0.f;
            #pragma unroll
            for (int kc = 0; kc < 4; kc++) {
                const int kc2 = kc * 8;
                uint32_t ah[4], al[4];
                ah[0] = Qwh[wr0 * SQ + kc2 + l4];
                ah[1] = Qwh[(wr0 + 8) * SQ + kc2 + l4];
                ah[2] = Qwh[wr0 * SQ + kc2 + l4 + 4];
                ah[3] = Qwh[(wr0 + 8) * SQ + kc2 + l4 + 4];
                al[0] = Qwl[wr0 * SQ + kc2 + l4];
                al[1] = Qwl[(wr0 + 8) * SQ + kc2 + l4];
                al[2] = Qwl[wr0 * SQ + kc2 + l4 + 4];
                al[3] = Qwl[(wr0 + 8) * SQ + kc2 + l4 + 4];
                #pragma unroll
                for (int an = 0; an < 4; an++) {
                    int n = colbase + an * 8 + g4;
                    uint32_t bh[2] = {Kh[n * SQ + kc2 + l4], Kh[n * SQ + kc2 + l4 + 4]};
                    uint32_t bl[2] = {Kl[n * SQ + kc2 + l4], Kl[n * SQ + kc2 + l4 + 4]};
                    mma16(s[an], ah, bh);
                    mma16(s[an], ah, bl);
                    mma16(s[an], al, bh);
                }
            }

            // ---- combine with rel-shifted BD + mask + scale ----
            float tmax[2] = {-1e30f, -1e30f};
            #pragma unroll
            for (int an = 0; an < 4; an++) {
                #pragma unroll
                for (int e = 0; e < 4; e++) {
                    int rh = e >> 1;
                    int di = wr0 + rh * 8;
                    int dj = colbase + an * 8 + 2 * l4 + (e & 1);
                    int i = i0 + di, j = j0 + dj;
                    float v = -1e30f;
                    if (di < validRows && j < TT) {
                        int jmaxr = (i < NMTOK) ? (NMTOK - 1)
                                  : ((i >= TT - NMTOK) ? (TT - 1) : i);
                        if (j <= jmaxr) {
                            float bd;
                            if (j <= i) {
                                int jr = TT - 1 - i + j;
                                bd = Ring[((jr >> 6) % 3) * RSLOT + di * RPAD + (jr & 63)];
                            } else if (j == i + 1) {
                                bd = 0.f;
                            } else {
                                // rare corner: reconstruct Qr row di+1 from planes
                                const float* rr = rbuf + (size_t)(j - i - 2) * DM + h * DH;
                                float accd = 0.f;
                                #pragma unroll 8
                                for (int d2 = 0; d2 < 32; d2++) {
                                    uint32_t wh = Qrh[(di + 1) * SQ + d2];
                                    uint32_t wl = Qrl[(di + 1) * SQ + d2];
                                    __nv_bfloat162 h2 = *reinterpret_cast<__nv_bfloat162*>(&wh);
                                    __nv_bfloat162 l2 = *reinterpret_cast<__nv_bfloat162*>(&wl);
                                    float q0 = __bfloat162float(h2.x) + __bfloat162float(l2.x);
                                    float q1 = __bfloat162float(h2.y) + __bfloat162float(l2.y);
                                    accd += q0 * rr[2 * d2] + q1 * rr[2 * d2 + 1];
                                }
                                bd = accd;
                            }
                            v = (s[an][e] + bd) * 0.125f;
                        }
                    }
                    s[an][e] = v;
                    tmax[rh] = fmaxf(tmax[rh], v);
                }
            }
            #pragma unroll
            for (int rh = 0; rh < 2; rh++) {
                tmax[rh] = fmaxf(tmax[rh], __shfl_xor_sync(0xffffffffu, tmax[rh], 1));
                tmax[rh] = fmaxf(tmax[rh], __shfl_xor_sync(0xffffffffu, tmax[rh], 2));
            }
            if (l4 == 0) {
                redm[wn * 64 + wm * 16 + g4]     = tmax[0];
                redm[wn * 64 + wm * 16 + g4 + 8] = tmax[1];
            }
            __syncthreads();

            float scl[2], lsum[2] = {0.f, 0.f};
            #pragma unroll
            for (int rh = 0; rh < 2; rh++) {
                int row = wm * 16 + g4 + rh * 8;
                float tm = fmaxf(redm[row], redm[64 + row]);
                float mnew = fmaxf(mrow[rh], tm);
                scl[rh] = expf(mrow[rh] - mnew);
                mrow[rh] = mnew;
            }
            #pragma unroll
            for (int an = 0; an < 4; an++) {
                #pragma unroll
                for (int e = 0; e < 4; e++) {
                    int rh = e >> 1;
                    float ev = expf(s[an][e] - mrow[rh]);
                    s[an][e] = ev;
                    lsum[rh] += ev;
                }
            }
            #pragma unroll
            for (int rh = 0; rh < 2; rh++) {
                lsum[rh] += __shfl_xor_sync(0xffffffffu, lsum[rh], 1);
                lsum[rh] += __shfl_xor_sync(0xffffffffu, lsum[rh], 2);
            }
            if (l4 == 0) {
                reds[wn * 64 + wm * 16 + g4]     = lsum[0];
                reds[wn * 64 + wm * 16 + g4 + 8] = lsum[1];
            }
            // stage P into packed pair planes (own rows only)
            #pragma unroll
            for (int an = 0; an < 4; an++) {
                int cp = (colbase >> 1) + an * 4 + l4;
                uint32_t hw, lw;
                split2(s[an][0], s[an][1], hw, lw);
                Ph[wr0 * SQ + cp] = hw; Pl[wr0 * SQ + cp] = lw;
                split2(s[an][2], s[an][3], hw, lw);
                Ph[(wr0 + 8) * SQ + cp] = hw; Pl[(wr0 + 8) * SQ + cp] = lw;
            }
            __syncthreads();

            #pragma unroll
            for (int rh = 0; rh < 2; rh++) {
                int row = wm * 16 + g4 + rh * 8;
                lrow[rh] = lrow[rh] * scl[rh] + reds[row] + reds[64 + row];
            }
            #pragma unroll
            for (int an = 0; an < 4; an++) {
                o[an][0] *= scl[0]; o[an][1] *= scl[0];
                o[an][2] *= scl[1]; o[an][3] *= scl[1];
            }

            // ---- PV MMA ----
            #pragma unroll
            for (int kc = 0; kc < 4; kc++) {
                const int kc2 = kc * 8;
                uint32_t ah[4], al[4];
                ah[0] = Ph[wr0 * SQ + kc2 + l4];
                ah[1] = Ph[(wr0 + 8) * SQ + kc2 + l4];
                ah[2] = Ph[wr0 * SQ + kc2 + l4 + 4];
                ah[3] = Ph[(wr0 + 8) * SQ + kc2 + l4 + 4];
                al[0] = Pl[wr0 * SQ + kc2 + l4];
                al[1] = Pl[(wr0 + 8) * SQ + kc2 + l4];
                al[2] = Pl[wr0 * SQ + kc2 + l4 + 4];
                al[3] = Pl[(wr0 + 8) * SQ + kc2 + l4 + 4];
                #pragma unroll
                for (int an = 0; an < 4; an++) {
                    int n = colbase + an * 8 + g4;
                    uint32_t bh[2] = {Vth[n * SV + kc2 + l4], Vth[n * SV + kc2 + l4 + 4]};
                    uint32_t bl[2] = {Vtl[n * SV + kc2 + l4], Vtl[n * SV + kc2 + l4 + 4]};
                    mma16(o[an], ah, bh);
                    mma16(o[an], ah, bl);
                    mma16(o[an], al, bh);
                }
            }
        } // j-tiles

        float inv0 = 1.f / lrow[0], inv1 = 1.f / lrow[1];
        #pragma unroll
        for (int an = 0; an < 4; an++) {
            int col = h * DH + colbase + an * 8 + 2 * l4;
            int r0 = i0 + wr0;
            if (wr0 < validRows) {
                av[(size_t)r0 * DM + col]     = o[an][0] * inv0;
                av[(size_t)r0 * DM + col + 1] = o[an][1] * inv0;
            }
            if (wr0 + 8 < validRows) {
                av[(size_t)(r0 + 8) * DM + col]     = o[an][2] * inv1;
                av[(size_t)(r0 + 8) * DM + col + 1] = o[an][3] * inv1;
            }
        }
    } // blocks
}

// ---------------- residual add + layernorm ----------------
__global__ void add_ln_kernel(float* __restrict__ w, const float* __restrict__ delta,
                              const float* __restrict__ gam, const float* __restrict__ bta) {
    int row = blockIdx.x;
    int tid = threadIdx.x;
    __shared__ float red[256];
    float x0 = w[row * DM + tid]       + delta[row * DM + tid];
    float x1 = w[row * DM + tid + 256] + delta[row * DM + tid + 256];
    red[tid] = x0 + x1; __syncthreads();
    for (int s = 128; s > 0; s >>= 1) {
        if (tid < s) red[tid] += red[tid + s];
        __syncthreads();
    }
    float mean = red[0] * (1.f / DM);
    __syncthreads();
    float d0 = x0 - mean, d1 = x1 - mean;
    red[tid] = d0 * d0 + d1 * d1; __syncthreads();
    for (int s = 128; s > 0; s >>= 1) {
        if (tid < s) red[tid] += red[tid + s];
        __syncthreads();
    }
    float inv = 1.f / sqrtf(red[0] * (1.f / DM) + 1e-5f);
    w[row * DM + tid]       = d0 * inv * gam[tid]       + bta[tid];
    w[row * DM + tid + 256] = d1 * inv * gam[tid + 256] + bta[tid + 256];
}

__global__ void copy_out_kernel(float* __restrict__ out) {
    int idx = blockIdx.x * blockDim.x + threadIdx.x;
    if (idx < TT * DM) out[idx] = g_w[idx];
}

// ---------------- launcher ----------------
extern "C" void kernel_launch(void* const* d_in, const int* in_sizes, int n_in,
                              void* d_out, int out_size) {
    (void)in_sizes; (void)n_in; (void)out_size;
    const float* word_emb = (const float*)d_in[0];
    const float* mem_tok  = (const float*)d_in[1];
    const float* Wqkv     = (const float*)d_in[2];
    const float* Wr       = (const float*)d_in[3];
    const float* Wo       = (const float*)d_in[4];
    const float* ln1s     = (const float*)d_in[5];
    const float* ln1b     = (const float*)d_in[6];
    const float* W1       = (const float*)d_in[7];
    const float* b1       = (const float*)d_in[8];
    const float* W2       = (const float*)d_in[9];
    const float* b2       = (const float*)d_in[10];
    const float* ln2s     = (const float*)d_in[11];
    const float* ln2b     = (const float*)d_in[12];
    const float* rwb      = (const float*)d_in[13];
    const float* rrb      = (const float*)d_in[14];

    float *g_w_p, *g_pos_p, *g_hd_p, *g_r_p, *g_av_p, *g_tmp_p, *g_ff1_p;
    cudaGetSymbolAddress((void**)&g_w_p,   g_w);
    cudaGetSymbolAddress((void**)&g_pos_p, g_pos);
    cudaGetSymbolAddress((void**)&g_hd_p,  g_heads);
    cudaGetSymbolAddress((void**)&g_r_p,   g_r);
    cudaGetSymbolAddress((void**)&g_av_p,  g_av);
    cudaGetSymbolAddress((void**)&g_tmp_p, g_tmp);
    cudaGetSymbolAddress((void**)&g_ff1_p, g_ff1);

    cudaFuncSetAttribute(fused_attn_kernel,
                         cudaFuncAttributeMaxDynamicSharedMemorySize, ATTN_SMEM);

    const int TD = TT * DM;
    build_w_kernel<<<(TD + 255) / 256, 256>>>(word_emb, mem_tok);
    build_pos_kernel<<<(TD + 255) / 256, 256>>>();

    const int MB = (TT + 127) / 128;   // 17

    for (int l = 0; l < NLAY; l++) {
        mma_gemm<<<dim3(3 * DM / 64, MB, 1), 256>>>(
            g_w_p, DM, Wqkv + (size_t)l * DM * 3 * DM, 3 * DM,
            g_hd_p, 3 * DM, nullptr, 0, TT, 3 * DM, DM);
        mma_gemm<<<dim3(DM / 64, MB, 1), 256>>>(
            g_pos_p, DM, Wr + (size_t)l * DM * DM, DM,
            g_r_p, DM, nullptr, 0, TT, DM, DM);

        fused_attn_kernel<<<dim3(NH, 17), 256, ATTN_SMEM>>>(
            g_hd_p, g_r_p, rwb, rrb, g_av_p);

        mma_gemm<<<dim3(DM / 64, MB, 1), 256>>>(
            g_av_p, DM, Wo + (size_t)l * DM * DM, DM,
            g_tmp_p, DM, nullptr, 0, TT, DM, DM);
        add_ln_kernel<<<TT, 256>>>(g_w_p, g_tmp_p, ln1s + l * DM, ln1b + l * DM);
        mma_gemm<<<dim3(DI / 64, MB, 1), 256>>>(
            g_w_p, DM, W1 + (size_t)l * DM * DI, DI,
            g_ff1_p, DI, b1 + (size_t)l * DI, 1, TT, DI, DM);
        mma_gemm<<<dim3(DM / 64, MB, 1), 256>>>(
            g_ff1_p, DI, W2 + (size_t)l * DI * DM, DM,
            g_tmp_p, DM, b2 + (size_t)l * DM, 0, TT, DM, DI);
        add_ln_kernel<<<TT, 256>>>(g_w_p, g_tmp_p, ln2s + l * DM, ln2b + l * DM);
    }

    copy_out_kernel<<<(TD + 255) / 256, 256>>>((float*)d_out);
}

// round 7
// speedup vs baseline: 1.9955x; 1.2208x over previous
#include <cuda_runtime.h>
#include <cuda_bf16.h>
#include <math.h>
#include <stdint.h>

// ---------------- problem constants ----------------
#define TT    2080
#define DM    512
#define NH    8
#define DH    64
#define DI    2048
#define NLAY  4
#define NMTOK 16
#define QL    2048

// ---------------- scratch ----------------
__device__ float g_w[TT * DM];
__device__ float g_pos[TT * DM];
__device__ float g_heads[TT * 3 * DM];
__device__ float g_r[TT * DM];
__device__ float g_av[TT * DM];
__device__ float g_tmp[TT * DM];
__device__ float g_ff1[TT * DI];

// ---------------- prep kernels ----------------
__global__ void build_w_kernel(const float* __restrict__ word_emb,
                               const float* __restrict__ mem) {
    int idx = blockIdx.x * blockDim.x + threadIdx.x;
    if (idx >= TT * DM) return;
    int row = idx / DM, c = idx % DM;
    float v;
    if (row < NMTOK)            v = mem[row * DM + c];
    else if (row < NMTOK + QL)  v = word_emb[(row - NMTOK) * DM + c];
    else                        v = mem[(row - NMTOK - QL) * DM + c];
    g_w[idx] = v;
}

__global__ void build_pos_kernel() {
    int idx = blockIdx.x * blockDim.x + threadIdx.x;
    if (idx >= TT * DM) return;
    int row = idx / DM, c = idx % DM;
    int f = (c < DM / 2) ? c : (c - DM / 2);
    double invf = exp(-((double)(2 * f) / (double)DM) * log(10000.0));
    double val = (double)(TT - 1 - row) * invf;
    g_pos[idx] = (float)((c < DM / 2) ? sin(val) : cos(val));
}

// ---------------- bf16x3 + ldmatrix helpers ----------------
__device__ __forceinline__ void split2(float x0, float x1, uint32_t& hw, uint32_t& lw) {
    __nv_bfloat162 h, l;
    h.x = __float2bfloat16(x0);
    h.y = __float2bfloat16(x1);
    l.x = __float2bfloat16(x0 - __bfloat162float(h.x));
    l.y = __float2bfloat16(x1 - __bfloat162float(h.y));
    hw = *reinterpret_cast<uint32_t*>(&h);
    lw = *reinterpret_cast<uint32_t*>(&l);
}

__device__ __forceinline__ void mma16(float (&c)[4], const uint32_t (&a)[4],
                                      uint32_t b0, uint32_t b1) {
    asm volatile(
        "mma.sync.aligned.m16n8k16.row.col.f32.bf16.bf16.f32 "
        "{%0,%1,%2,%3}, {%4,%5,%6,%7}, {%8,%9}, {%0,%1,%2,%3};"
        : "+f"(c[0]), "+f"(c[1]), "+f"(c[2]), "+f"(c[3])
        : "r"(a[0]), "r"(a[1]), "r"(a[2]), "r"(a[3]), "r"(b0), "r"(b1));
}

__device__ __forceinline__ uint32_t sm_u32(const void* p) {
    return (uint32_t)__cvta_generic_to_shared(p);
}

__device__ __forceinline__ void ldsm4(uint32_t (&r)[4], uint32_t a) {
    asm volatile("ldmatrix.sync.aligned.m8n8.x4.shared.b16 {%0,%1,%2,%3}, [%4];"
                 : "=r"(r[0]), "=r"(r[1]), "=r"(r[2]), "=r"(r[3]) : "r"(a));
}

// B-style pair-plane layout: word index for row n = n*36 + (n>>3)*4 (+ kpair)
__device__ __forceinline__ int boff(int n) { return n * 36 + ((n >> 3) << 2); }
#define BPLANE (64 * 36 + 32)

// ---------------- projection GEMM (bf16x3, NN, ldmatrix) ----------------
#define PPA 20   // A plane row stride (words)

__global__ __launch_bounds__(256, 2)
void mma_gemm(const float* __restrict__ A, int lda,
              const float* __restrict__ B, int ldb,
              float* __restrict__ C, int ldc,
              const float* __restrict__ cbias, int doRelu,
              int M, int N, int K) {
    __shared__ uint32_t Ah[128 * PPA], Al[128 * PPA];
    __shared__ uint32_t Bh[BPLANE], Bl[BPLANE];

    const int bm = blockIdx.y * 128, bn = blockIdx.x * 64;
    const int tid = threadIdx.x;
    const int lane = tid & 31, warp = tid >> 5;
    const int wm = warp & 3, wn = warp >> 2;
    const int g4 = lane >> 2, l4 = lane & 3;

    float acc[2][4][4] = {};
    float4 pa[4], pb[2];

    const int ar = tid >> 3, ak4 = (tid & 7) * 4;
    const int bkp = tid >> 4, bn4 = (tid & 15) * 4;

    // ldmatrix addresses
    const int aRow = lane & 15;
    const uint32_t aHiB = ((lane >> 4) & 1) * 16;
    const uint32_t adAh = sm_u32(Ah) + (uint32_t)((wm * 32 + aRow) * PPA) * 4 + aHiB;
    const uint32_t adAl = sm_u32(Al) + (uint32_t)((wm * 32 + aRow) * PPA) * 4 + aHiB;
    const int bRowN = ((lane >> 4) & 1) * 8 + (lane & 7);
    const uint32_t bHiB = ((lane >> 3) & 1) * 16;
    const uint32_t adBh0 = sm_u32(Bh) + (uint32_t)boff(wn * 32 + bRowN) * 4 + bHiB;
    const uint32_t adBh1 = sm_u32(Bh) + (uint32_t)boff(wn * 32 + 16 + bRowN) * 4 + bHiB;
    const uint32_t adBl0 = sm_u32(Bl) + (uint32_t)boff(wn * 32 + bRowN) * 4 + bHiB;
    const uint32_t adBl1 = sm_u32(Bl) + (uint32_t)boff(wn * 32 + 16 + bRowN) * 4 + bHiB;

    auto loadA = [&](int k0) {
        #pragma unroll
        for (int p = 0; p < 4; p++) {
            int row = bm + p * 32 + ar;
            float4 v = make_float4(0.f, 0.f, 0.f, 0.f);
            if (row < M) v = *reinterpret_cast<const float4*>(A + (size_t)row * lda + k0 + ak4);
            pa[p] = v;
        }
    };
    auto loadB = [&](int k0) {
        pb[0] = *reinterpret_cast<const float4*>(B + (size_t)(k0 + 2 * bkp) * ldb + bn + bn4);
        pb[1] = *reinterpret_cast<const float4*>(B + (size_t)(k0 + 2 * bkp + 1) * ldb + bn + bn4);
    };
    auto storeAB = [&]() {
        #pragma unroll
        for (int p = 0; p < 4; p++) {
            int row = p * 32 + ar;
            uint32_t h0, l0, h1, l1;
            split2(pa[p].x, pa[p].y, h0, l0);
            split2(pa[p].z, pa[p].w, h1, l1);
            int wi = row * PPA + (ak4 >> 1);
            Ah[wi] = h0; Ah[wi + 1] = h1;
            Al[wi] = l0; Al[wi + 1] = l1;
        }
        const float* p0 = &pb[0].x;
        const float* p1 = &pb[1].x;
        #pragma unroll
        for (int i = 0; i < 4; i++) {
            uint32_t hw, lw;
            split2(p0[i], p1[i], hw, lw);   // low = even k
            int wi = boff(bn4 + i) + bkp;
            Bh[wi] = hw; Bl[wi] = lw;
        }
    };

    loadA(0);
    loadB(0);

    for (int k0 = 0; k0 < K; k0 += 32) {
        storeAB();
        __syncthreads();
        if (k0 + 32 < K) { loadA(k0 + 32); loadB(k0 + 32); }

        #pragma unroll
        for (int ks = 0; ks < 2; ks++) {
            uint32_t ahh[2][4], alo[2][4];
            ldsm4(ahh[0], adAh + ks * 32);
            ldsm4(ahh[1], adAh + 16 * PPA * 4 + ks * 32);
            ldsm4(alo[0], adAl + ks * 32);
            ldsm4(alo[1], adAl + 16 * PPA * 4 + ks * 32);
            uint32_t bhh[2][4], blo[2][4];
            ldsm4(bhh[0], adBh0 + ks * 32);
            ldsm4(bhh[1], adBh1 + ks * 32);
            ldsm4(blo[0], adBl0 + ks * 32);
            ldsm4(blo[1], adBl1 + ks * 32);
            #pragma unroll
            for (int am = 0; am < 2; am++)
                #pragma unroll
                for (int an = 0; an < 4; an++) {
                    const int g = an >> 1, x = (an & 1) * 2;
                    mma16(acc[am][an], ahh[am], bhh[g][x], bhh[g][x + 1]);
                    mma16(acc[am][an], ahh[am], blo[g][x], blo[g][x + 1]);
                    mma16(acc[am][an], alo[am], bhh[g][x], bhh[g][x + 1]);
                }
        }
        __syncthreads();
    }

    #pragma unroll
    for (int am = 0; am < 2; am++) {
        int row0 = bm + wm * 32 + am * 16 + g4;
        #pragma unroll
        for (int an = 0; an < 4; an++) {
            int col0 = bn + wn * 32 + an * 8 + 2 * l4;
            float v0 = acc[am][an][0], v1 = acc[am][an][1];
            float v2 = acc[am][an][2], v3 = acc[am][an][3];
            if (cbias) {
                float b0 = cbias[col0], b1 = cbias[col0 + 1];
                v0 += b0; v1 += b1; v2 += b0; v3 += b1;
            }
            if (doRelu) {
                v0 = fmaxf(v0, 0.f); v1 = fmaxf(v1, 0.f);
                v2 = fmaxf(v2, 0.f); v3 = fmaxf(v3, 0.f);
            }
            if (row0 < M) {
                C[(size_t)row0 * ldc + col0]     = v0;
                C[(size_t)row0 * ldc + col0 + 1] = v1;
            }
            if (row0 + 8 < M) {
                C[(size_t)(row0 + 8) * ldc + col0]     = v2;
                C[(size_t)(row0 + 8) * ldc + col0 + 1] = v3;
            }
        }
    }
}

// ---------------- fused flash-style relative attention (bf16x3 + ldmatrix) ----------------
#define RPAD 68
#define RSLOT (64 * RPAD)
#define ATTN_WORDS (12 * BPLANE + 3 * RSLOT + 256)
#define ATTN_SMEM (ATTN_WORDS * 4)

__global__ __launch_bounds__(256, 1)
void fused_attn_kernel(const float* __restrict__ heads,
                       const float* __restrict__ rbuf,
                       const float* __restrict__ rwb,
                       const float* __restrict__ rrb,
                       float* __restrict__ av) {
    extern __shared__ uint32_t smu[];
    uint32_t* Qwh = smu;
    uint32_t* Qwl = Qwh + BPLANE;
    uint32_t* Qrh = Qwl + BPLANE;
    uint32_t* Qrl = Qrh + BPLANE;
    uint32_t* Kh  = Qrl + BPLANE;
    uint32_t* Kl  = Kh  + BPLANE;
    uint32_t* Rh  = Kl  + BPLANE;
    uint32_t* Rl  = Rh  + BPLANE;
    uint32_t* Vth = Rl  + BPLANE;
    uint32_t* Vtl = Vth + BPLANE;
    uint32_t* Ph  = Vtl + BPLANE;
    uint32_t* Pl  = Ph  + BPLANE;
    float* Ring = (float*)(Pl + BPLANE);
    float* redm = Ring + 3 * RSLOT;
    float* reds = redm + 128;

    const int h = blockIdx.x;
    const int p = blockIdx.y;
    const int tid = threadIdx.x;
    const int lane = tid & 31, warp = tid >> 5;
    const int wm = warp & 3, wn = warp >> 2;
    const int g4 = lane >> 2, l4 = lane & 3;
    const int wr0 = wm * 16 + g4;
    const int colbase = wn * 32;

    // ldmatrix addresses
    const int aRow = lane & 15;
    const uint32_t aHiB = ((lane >> 4) & 1) * 16;
    const uint32_t aOff = (uint32_t)boff(wm * 16 + aRow) * 4 + aHiB;
    const uint32_t adQwh = sm_u32(Qwh) + aOff, adQwl = sm_u32(Qwl) + aOff;
    const uint32_t adQrh = sm_u32(Qrh) + aOff, adQrl = sm_u32(Qrl) + aOff;
    const uint32_t adPh  = sm_u32(Ph)  + aOff, adPl  = sm_u32(Pl)  + aOff;
    const int bRowN = ((lane >> 4) & 1) * 8 + (lane & 7);
    const uint32_t bHiB = ((lane >> 3) & 1) * 16;
    const uint32_t bO0 = (uint32_t)boff(colbase + bRowN) * 4 + bHiB;
    const uint32_t bO1 = (uint32_t)boff(colbase + 16 + bRowN) * 4 + bHiB;
    const uint32_t adKh0 = sm_u32(Kh) + bO0,  adKh1 = sm_u32(Kh) + bO1;
    const uint32_t adKl0 = sm_u32(Kl) + bO0,  adKl1 = sm_u32(Kl) + bO1;
    const uint32_t adRh0 = sm_u32(Rh) + bO0,  adRh1 = sm_u32(Rh) + bO1;
    const uint32_t adRl0 = sm_u32(Rl) + bO0,  adRl1 = sm_u32(Rl) + bO1;
    const uint32_t adVh0 = sm_u32(Vth) + bO0, adVh1 = sm_u32(Vth) + bO1;
    const uint32_t adVl0 = sm_u32(Vtl) + bO0, adVl1 = sm_u32(Vtl) + bO1;

    int blist[2]; int nblk;
    if (p < 16) { blist[0] = p; blist[1] = 31 - p; nblk = 2; }
    else        { blist[0] = 32; nblk = 1; }

    for (int bi = 0; bi < nblk; bi++) {
        const int b = blist[bi];
        const int i0 = b * 64;
        const int validRows = min(64, TT - i0);
        const int njt = (b < 32) ? (b + 1) : 33;

        __syncthreads();
        // Load Q (+ biases), pre-split into pair planes
        for (int t = tid; t < 64 * 16; t += 256) {
            int r = t >> 4, c4 = (t & 15) * 4;
            int grow = i0 + r;
            float4 q = make_float4(0.f, 0.f, 0.f, 0.f);
            if (grow < TT)
                q = *(const float4*)(heads + (size_t)grow * (3 * DM) + h * DH + c4);
            float4 bw = *(const float4*)(rwb + h * DH + c4);
            float4 br = *(const float4*)(rrb + h * DH + c4);
            int wi = boff(r) + (c4 >> 1);
            uint32_t hw, lw;
            split2(q.x + bw.x, q.y + bw.y, hw, lw); Qwh[wi] = hw;     Qwl[wi] = lw;
            split2(q.z + bw.z, q.w + bw.w, hw, lw); Qwh[wi + 1] = hw; Qwl[wi + 1] = lw;
            split2(q.x + br.x, q.y + br.y, hw, lw); Qrh[wi] = hw;     Qrl[wi] = lw;
            split2(q.z + br.z, q.w + br.w, hw, lw); Qrh[wi + 1] = hw; Qrl[wi + 1] = lw;
        }

        float o[4][4];
        #pragma unroll
        for (int a = 0; a < 4; a++) { o[a][0] = o[a][1] = o[a][2] = o[a][3] = 0.f; }
        float mrow[2] = {-1e30f, -1e30f};
        float lrow[2] = {0.f, 0.f};

        int nextChunk = (2016 - i0) / 64;
        if (nextChunk < 0) nextChunk = 0;

        for (int jt = 0; jt < njt; jt++) {
            const int j0 = jt * 64;

            // ---- build BDraw chunks ----
            const int hiJr = min(TT - 1, TT - 1 - i0 + j0 + 63);
            const int chi = hiJr >> 6;
            while (nextChunk <= chi) {
                const int c = nextChunk;
                __syncthreads();
                for (int t = tid; t < 64 * 16; t += 256) {
                    int r = t >> 4, c4 = (t & 15) * 4;
                    int grow = c * 64 + r;
                    float4 v = make_float4(0.f, 0.f, 0.f, 0.f);
                    if (grow < TT)
                        v = *(const float4*)(rbuf + (size_t)grow * DM + h * DH + c4);
                    int wi = boff(r) + (c4 >> 1);
                    uint32_t hw, lw;
                    split2(v.x, v.y, hw, lw); Rh[wi] = hw;     Rl[wi] = lw;
                    split2(v.z, v.w, hw, lw); Rh[wi + 1] = hw; Rl[wi + 1] = lw;
                }
                __syncthreads();
                float cacc[4][4];
                #pragma unroll
                for (int a = 0; a < 4; a++)
                    cacc[a][0] = cacc[a][1] = cacc[a][2] = cacc[a][3] = 0.f;
                #pragma unroll
                for (int kc = 0; kc < 4; kc++) {
                    uint32_t ah[4], al[4];
                    ldsm4(ah, adQrh + kc * 32);
                    ldsm4(al, adQrl + kc * 32);
                    uint32_t bh[2][4], bl[2][4];
                    ldsm4(bh[0], adRh0 + kc * 32);
                    ldsm4(bh[1], adRh1 + kc * 32);
                    ldsm4(bl[0], adRl0 + kc * 32);
                    ldsm4(bl[1], adRl1 + kc * 32);
                    #pragma unroll
                    for (int an = 0; an < 4; an++) {
                        const int g = an >> 1, x = (an & 1) * 2;
                        mma16(cacc[an], ah, bh[g][x], bh[g][x + 1]);
                        mma16(cacc[an], ah, bl[g][x], bl[g][x + 1]);
                        mma16(cacc[an], al, bh[g][x], bh[g][x + 1]);
                    }
                }
                float* slot = Ring + (c % 3) * RSLOT;
                #pragma unroll
                for (int an = 0; an < 4; an++) {
                    int col = colbase + an * 8 + 2 * l4;
                    slot[wr0 * RPAD + col]           = cacc[an][0];
                    slot[wr0 * RPAD + col + 1]       = cacc[an][1];
                    slot[(wr0 + 8) * RPAD + col]     = cacc[an][2];
                    slot[(wr0 + 8) * RPAD + col + 1] = cacc[an][3];
                }
                nextChunk++;
            }

            // ---- load K tile (pair planes) + V tile (transposed pair planes) ----
            __syncthreads();
            for (int t = tid; t < 64 * 16; t += 256) {
                int r = t >> 4, c4 = (t & 15) * 4;
                int grow = j0 + r;
                float4 kv = make_float4(0.f, 0.f, 0.f, 0.f);
                if (grow < TT)
                    kv = *(const float4*)(heads + (size_t)grow * (3 * DM) + DM + h * DH + c4);
                int wi = boff(r) + (c4 >> 1);
                uint32_t hw, lw;
                split2(kv.x, kv.y, hw, lw); Kh[wi] = hw;     Kl[wi] = lw;
                split2(kv.z, kv.w, hw, lw); Kh[wi + 1] = hw; Kl[wi + 1] = lw;
            }
            {   // V transpose: thread owns key-pair kp, 8 features
                int kp = tid >> 3, fb = (tid & 7) * 8;
                int jA = j0 + 2 * kp, jB = jA + 1;
                float4 a0 = make_float4(0.f, 0.f, 0.f, 0.f), a1 = a0, b0 = a0, b1 = a0;
                if (jA < TT) {
                    a0 = *(const float4*)(heads + (size_t)jA * (3 * DM) + 2 * DM + h * DH + fb);
                    a1 = *(const float4*)(heads + (size_t)jA * (3 * DM) + 2 * DM + h * DH + fb + 4);
                }
                if (jB < TT) {
                    b0 = *(const float4*)(heads + (size_t)jB * (3 * DM) + 2 * DM + h * DH + fb);
                    b1 = *(const float4*)(heads + (size_t)jB * (3 * DM) + 2 * DM + h * DH + fb + 4);
                }
                const float* pa0 = &a0.x; const float* pa1 = &a1.x;
                const float* pb0 = &b0.x; const float* pb1 = &b1.x;
                #pragma unroll
                for (int i = 0; i < 4; i++) {
                    uint32_t hw, lw;
                    split2(pa0[i], pb0[i], hw, lw);           // low = even key
                    Vth[boff(fb + i) + kp] = hw; Vtl[boff(fb + i) + kp] = lw;
                    split2(pa1[i], pb1[i], hw, lw);
                    Vth[boff(fb + 4 + i) + kp] = hw; Vtl[boff(fb + 4 + i) + kp] = lw;
                }
            }
            __syncthreads();

            // ---- AC MMA ----
            float s[4][4];
            #pragma unroll
            for (int a = 0; a < 4; a++)
                s[a][0] = s[a][1] = s[a][2] = s[a][3] = 0.f;
            #pragma unroll
            for (int kc = 0; kc < 4; kc++) {
                uint32_t ah[4], al[4];
                ldsm4(ah, adQwh + kc * 32);
                ldsm4(al, adQwl + kc * 32);
                uint32_t bh[2][4], bl[2][4];
                ldsm4(bh[0], adKh0 + kc * 32);
                ldsm4(bh[1], adKh1 + kc * 32);
                ldsm4(bl[0], adKl0 + kc * 32);
                ldsm4(bl[1], adKl1 + kc * 32);
                #pragma unroll
                for (int an = 0; an < 4; an++) {
                    const int g = an >> 1, x = (an & 1) * 2;
                    mma16(s[an], ah, bh[g][x], bh[g][x + 1]);
                    mma16(s[an], ah, bl[g][x], bl[g][x + 1]);
                    mma16(s[an], al, bh[g][x], bh[g][x + 1]);
                }
            }

            // ---- combine with rel-shifted BD + mask + scale ----
            float tmax[2] = {-1e30f, -1e30f};
            #pragma unroll
            for (int an = 0; an < 4; an++) {
                #pragma unroll
                for (int e = 0; e < 4; e++) {
                    int rh = e >> 1;
                    int di = wr0 + rh * 8;
                    int dj = colbase + an * 8 + 2 * l4 + (e & 1);
                    int i = i0 + di, j = j0 + dj;
                    float v = -1e30f;
                    if (di < validRows && j < TT) {
                        int jmaxr = (i < NMTOK) ? (NMTOK - 1)
                                  : ((i >= TT - NMTOK) ? (TT - 1) : i);
                        if (j <= jmaxr) {
                            float bd;
                            if (j <= i) {
                                int jr = TT - 1 - i + j;
                                bd = Ring[((jr >> 6) % 3) * RSLOT + di * RPAD + (jr & 63)];
                            } else if (j == i + 1) {
                                bd = 0.f;
                            } else {
                                const float* rr = rbuf + (size_t)(j - i - 2) * DM + h * DH;
                                float accd = 0.f;
                                #pragma unroll 8
                                for (int d2 = 0; d2 < 32; d2++) {
                                    uint32_t wh = Qrh[boff(di + 1) + d2];
                                    uint32_t wl = Qrl[boff(di + 1) + d2];
                                    __nv_bfloat162 h2 = *reinterpret_cast<__nv_bfloat162*>(&wh);
                                    __nv_bfloat162 l2 = *reinterpret_cast<__nv_bfloat162*>(&wl);
                                    float q0 = __bfloat162float(h2.x) + __bfloat162float(l2.x);
                                    float q1 = __bfloat162float(h2.y) + __bfloat162float(l2.y);
                                    accd += q0 * rr[2 * d2] + q1 * rr[2 * d2 + 1];
                                }
                                bd = accd;
                            }
                            v = (s[an][e] + bd) * 0.125f;
                        }
                    }
                    s[an][e] = v;
                    tmax[rh] = fmaxf(tmax[rh], v);
                }
            }
            #pragma unroll
            for (int rh = 0; rh < 2; rh++) {
                tmax[rh] = fmaxf(tmax[rh], __shfl_xor_sync(0xffffffffu, tmax[rh], 1));
                tmax[rh] = fmaxf(tmax[rh], __shfl_xor_sync(0xffffffffu, tmax[rh], 2));
            }
            if (l4 == 0) {
                redm[wn * 64 + wm * 16 + g4]     = tmax[0];
                redm[wn * 64 + wm * 16 + g4 + 8] = tmax[1];
            }
            __syncthreads();

            float scl[2], lsum[2] = {0.f, 0.f};
            #pragma unroll
            for (int rh = 0; rh < 2; rh++) {
                int row = wm * 16 + g4 + rh * 8;
                float tm = fmaxf(redm[row], redm[64 + row]);
                float mnew = fmaxf(mrow[rh], tm);
                scl[rh] = expf(mrow[rh] - mnew);
                mrow[rh] = mnew;
            }
            #pragma unroll
            for (int an = 0; an < 4; an++) {
                #pragma unroll
                for (int e = 0; e < 4; e++) {
                    int rh = e >> 1;
                    float ev = expf(s[an][e] - mrow[rh]);
                    s[an][e] = ev;
                    lsum[rh] += ev;
                }
            }
            #pragma unroll
            for (int rh = 0; rh < 2; rh++) {
                lsum[rh] += __shfl_xor_sync(0xffffffffu, lsum[rh], 1);
                lsum[rh] += __shfl_xor_sync(0xffffffffu, lsum[rh], 2);
            }
            if (l4 == 0) {
                reds[wn * 64 + wm * 16 + g4]     = lsum[0];
                reds[wn * 64 + wm * 16 + g4 + 8] = lsum[1];
            }
            // stage P into packed pair planes
            #pragma unroll
            for (int an = 0; an < 4; an++) {
                int cp = (colbase >> 1) + an * 4 + l4;
                uint32_t hw, lw;
                split2(s[an][0], s[an][1], hw, lw);
                Ph[boff(wr0) + cp] = hw; Pl[boff(wr0) + cp] = lw;
                split2(s[an][2], s[an][3], hw, lw);
                Ph[boff(wr0 + 8) + cp] = hw; Pl[boff(wr0 + 8) + cp] = lw;
            }
            __syncthreads();

            #pragma unroll
            for (int rh = 0; rh < 2; rh++) {
                int row = wm * 16 + g4 + rh * 8;
                lrow[rh] = lrow[rh] * scl[rh] + reds[row] + reds[64 + row];
            }
            #pragma unroll
            for (int an = 0; an < 4; an++) {
                o[an][0] *= scl[0]; o[an][1] *= scl[0];
                o[an][2] *= scl[1]; o[an][3] *= scl[1];
            }

            // ---- PV MMA ----
            #pragma unroll
            for (int kc = 0; kc < 4; kc++) {
                uint32_t ah[4], al[4];
                ldsm4(ah, adPh + kc * 32);
                ldsm4(al, adPl + kc * 32);
                uint32_t bh[2][4], bl[2][4];
                ldsm4(bh[0], adVh0 + kc * 32);
                ldsm4(bh[1], adVh1 + kc * 32);
                ldsm4(bl[0], adVl0 + kc * 32);
                ldsm4(bl[1], adVl1 + kc * 32);
                #pragma unroll
                for (int an = 0; an < 4; an++) {
                    const int g = an >> 1, x = (an & 1) * 2;
                    mma16(o[an], ah, bh[g][x], bh[g][x + 1]);
                    mma16(o[an], ah, bl[g][x], bl[g][x + 1]);
                    mma16(o[an], al, bh[g][x], bh[g][x + 1]);
                }
            }
        } // j-tiles

        float inv0 = 1.f / lrow[0], inv1 = 1.f / lrow[1];
        #pragma unroll
        for (int an = 0; an < 4; an++) {
            int col = h * DH + colbase + an * 8 + 2 * l4;
            int r0 = i0 + wr0;
            if (wr0 < validRows) {
                av[(size_t)r0 * DM + col]     = o[an][0] * inv0;
                av[(size_t)r0 * DM + col + 1] = o[an][1] * inv0;
            }
            if (wr0 + 8 < validRows) {
                av[(size_t)(r0 + 8) * DM + col]     = o[an][2] * inv1;
                av[(size_t)(r0 + 8) * DM + col + 1] = o[an][3] * inv1;
            }
        }
    } // blocks
}

// ---------------- residual add + layernorm ----------------
__global__ void add_ln_kernel(float* __restrict__ w, const float* __restrict__ delta,
                              const float* __restrict__ gam, const float* __restrict__ bta) {
    int row = blockIdx.x;
    int tid = threadIdx.x;
    __shared__ float red[256];
    float x0 = w[row * DM + tid]       + delta[row * DM + tid];
    float x1 = w[row * DM + tid + 256] + delta[row * DM + tid + 256];
    red[tid] = x0 + x1; __syncthreads();
    for (int s = 128; s > 0; s >>= 1) {
        if (tid < s) red[tid] += red[tid + s];
        __syncthreads();
    }
    float mean = red[0] * (1.f / DM);
    __syncthreads();
    float d0 = x0 - mean, d1 = x1 - mean;
    red[tid] = d0 * d0 + d1 * d1; __syncthreads();
    for (int s = 128; s > 0; s >>= 1) {
        if (tid < s) red[tid] += red[tid + s];
        __syncthreads();
    }
    float inv = 1.f / sqrtf(red[0] * (1.f / DM) + 1e-5f);
    w[row * DM + tid]       = d0 * inv * gam[tid]       + bta[tid];
    w[row * DM + tid + 256] = d1 * inv * gam[tid + 256] + bta[tid + 256];
}

__global__ void copy_out_kernel(float* __restrict__ out) {
    int idx = blockIdx.x * blockDim.x + threadIdx.x;
    if (idx < TT * DM) out[idx] = g_w[idx];
}

// ---------------- launcher ----------------
extern "C" void kernel_launch(void* const* d_in, const int* in_sizes, int n_in,
                              void* d_out, int out_size) {
    (void)in_sizes; (void)n_in; (void)out_size;
    const float* word_emb = (const float*)d_in[0];
    const float* mem_tok  = (const float*)d_in[1];
    const float* Wqkv     = (const float*)d_in[2];
    const float* Wr       = (const float*)d_in[3];
    const float* Wo       = (const float*)d_in[4];
    const float* ln1s     = (const float*)d_in[5];
    const float* ln1b     = (const float*)d_in[6];
    const float* W1       = (const float*)d_in[7];
    const float* b1       = (const float*)d_in[8];
    const float* W2       = (const float*)d_in[9];
    const float* b2       = (const float*)d_in[10];
    const float* ln2s     = (const float*)d_in[11];
    const float* ln2b     = (const float*)d_in[12];
    const float* rwb      = (const float*)d_in[13];
    const float* rrb      = (const float*)d_in[14];

    float *g_w_p, *g_pos_p, *g_hd_p, *g_r_p, *g_av_p, *g_tmp_p, *g_ff1_p;
    cudaGetSymbolAddress((void**)&g_w_p,   g_w);
    cudaGetSymbolAddress((void**)&g_pos_p, g_pos);
    cudaGetSymbolAddress((void**)&g_hd_p,  g_heads);
    cudaGetSymbolAddress((void**)&g_r_p,   g_r);
    cudaGetSymbolAddress((void**)&g_av_p,  g_av);
    cudaGetSymbolAddress((void**)&g_tmp_p, g_tmp);
    cudaGetSymbolAddress((void**)&g_ff1_p, g_ff1);

    cudaFuncSetAttribute(fused_attn_kernel,
                         cudaFuncAttributeMaxDynamicSharedMemorySize, ATTN_SMEM);

    const int TD = TT * DM;
    build_w_kernel<<<(TD + 255) / 256, 256>>>(word_emb, mem_tok);
    build_pos_kernel<<<(TD + 255) / 256, 256>>>();

    const int MB = (TT + 127) / 128;   // 17

    for (int l = 0; l < NLAY; l++) {
        mma_gemm<<<dim3(3 * DM / 64, MB, 1), 256>>>(
            g_w_p, DM, Wqkv + (size_t)l * DM * 3 * DM, 3 * DM,
            g_hd_p, 3 * DM, nullptr, 0, TT, 3 * DM, DM);
        mma_gemm<<<dim3(DM / 64, MB, 1), 256>>>(
            g_pos_p, DM, Wr + (size_t)l * DM * DM, DM,
            g_r_p, DM, nullptr, 0, TT, DM, DM);

        fused_attn_kernel<<<dim3(NH, 17), 256, ATTN_SMEM>>>(
            g_hd_p, g_r_p, rwb, rrb, g_av_p);

        mma_gemm<<<dim3(DM / 64, MB, 1), 256>>>(
            g_av_p, DM, Wo + (size_t)l * DM * DM, DM,
            g_tmp_p, DM, nullptr, 0, TT, DM, DM);
        add_ln_kernel<<<TT, 256>>>(g_w_p, g_tmp_p, ln1s + l * DM, ln1b + l * DM);
        mma_gemm<<<dim3(DI / 64, MB, 1), 256>>>(
            g_w_p, DM, W1 + (size_t)l * DM * DI, DI,
            g_ff1_p, DI, b1 + (size_t)l * DI, 1, TT, DI, DM);
        mma_gemm<<<dim3(DM / 64, MB, 1), 256>>>(
            g_ff1_p, DI, W2 + (size_t)l * DI * DM, DM,
            g_tmp_p, DM, b2 + (size_t)l * DM, 0, TT, DM, DI);
        add_ln_kernel<<<TT, 256>>>(g_w_p, g_tmp_p, ln2s + l * DM, ln2b + l * DM);
    }

    copy_out_kernel<<<(TD + 255) / 256, 256>>>((float*)d_out);
}

// round 8
// speedup vs baseline: 2.2452x; 1.1251x over previous
#include <cuda_runtime.h>
#include <cuda_bf16.h>
#include <math.h>
#include <stdint.h>

// ---------------- problem constants ----------------
#define TT    2080
#define DM    512
#define NH    8
#define DH    64
#define DI    2048
#define NLAY  4
#define NMTOK 16
#define QL    2048

// ---------------- scratch ----------------
__device__ float g_w[TT * DM];
__device__ float g_pos[TT * DM];
__device__ float g_heads[TT * 3 * DM];
__device__ float g_r[TT * DM];
__device__ float g_av[TT * DM];
__device__ float g_tmp[TT * DM];
__device__ float g_tmp2[TT * DM];
__device__ float g_ff1[TT * DI];

// ---------------- prep kernels ----------------
__global__ void build_w_kernel(const float* __restrict__ word_emb,
                               const float* __restrict__ mem) {
    int idx = blockIdx.x * blockDim.x + threadIdx.x;
    if (idx >= TT * DM) return;
    int row = idx / DM, c = idx % DM;
    float v;
    if (row < NMTOK)            v = mem[row * DM + c];
    else if (row < NMTOK + QL)  v = word_emb[(row - NMTOK) * DM + c];
    else                        v = mem[(row - NMTOK - QL) * DM + c];
    g_w[idx] = v;
}

__global__ void build_pos_kernel() {
    int idx = blockIdx.x * blockDim.x + threadIdx.x;
    if (idx >= TT * DM) return;
    int row = idx / DM, c = idx % DM;
    int f = (c < DM / 2) ? c : (c - DM / 2);
    double invf = exp(-((double)(2 * f) / (double)DM) * log(10000.0));
    double val = (double)(TT - 1 - row) * invf;
    g_pos[idx] = (float)((c < DM / 2) ? sin(val) : cos(val));
}

// ---------------- bf16x3 + ldmatrix helpers ----------------
__device__ __forceinline__ void split2(float x0, float x1, uint32_t& hw, uint32_t& lw) {
    __nv_bfloat162 h, l;
    h.x = __float2bfloat16(x0);
    h.y = __float2bfloat16(x1);
    l.x = __float2bfloat16(x0 - __bfloat162float(h.x));
    l.y = __float2bfloat16(x1 - __bfloat162float(h.y));
    hw = *reinterpret_cast<uint32_t*>(&h);
    lw = *reinterpret_cast<uint32_t*>(&l);
}

__device__ __forceinline__ void mma16(float (&c)[4], const uint32_t (&a)[4],
                                      uint32_t b0, uint32_t b1) {
    asm volatile(
        "mma.sync.aligned.m16n8k16.row.col.f32.bf16.bf16.f32 "
        "{%0,%1,%2,%3}, {%4,%5,%6,%7}, {%8,%9}, {%0,%1,%2,%3};"
        : "+f"(c[0]), "+f"(c[1]), "+f"(c[2]), "+f"(c[3])
        : "r"(a[0]), "r"(a[1]), "r"(a[2]), "r"(a[3]), "r"(b0), "r"(b1));
}

__device__ __forceinline__ uint32_t sm_u32(const void* p) {
    return (uint32_t)__cvta_generic_to_shared(p);
}

__device__ __forceinline__ void ldsm4(uint32_t (&r)[4], uint32_t a) {
    asm volatile("ldmatrix.sync.aligned.m8n8.x4.shared.b16 {%0,%1,%2,%3}, [%4];"
                 : "=r"(r[0]), "=r"(r[1]), "=r"(r[2]), "=r"(r[3]) : "r"(a));
}

// B-style pair-plane layout: word index for row n = n*36 + (n>>3)*4 (+ kpair)
__device__ __forceinline__ int boff(int n) { return n * 36 + ((n >> 3) << 2); }
#define BPLANE (64 * 36 + 32)

// ---------------- projection GEMM (bf16x3, NN, ldmatrix, double-buffered) ----------------
#define PPA 20   // A plane row stride (words)
#define ABUF (128 * PPA)                 // words per A buffer
#define GEMM_SMEM ((4 * ABUF + 4 * BPLANE) * 4)   // 2 bufs x (Ah,Al,Bh,Bl)

__global__ __launch_bounds__(256, 2)
void mma_gemm(const float* __restrict__ A, int lda,
              const float* __restrict__ B, int ldb,
              float* __restrict__ C, float* __restrict__ C2, int ldc,
              const float* __restrict__ cbias, int doRelu,
              int M, int N, int Ksub) {
    extern __shared__ uint32_t gsm[];
    uint32_t* Ah = gsm;                 // [2][ABUF]
    uint32_t* Al = Ah + 2 * ABUF;
    uint32_t* Bh = Al + 2 * ABUF;       // [2][BPLANE]
    uint32_t* Bl = Bh + 2 * BPLANE;

    const int bm = blockIdx.y * 128, bn = blockIdx.x * 64;
    const int kOff = blockIdx.z * Ksub;
    if (blockIdx.z == 1) C = C2;
    const float* Ag = A + kOff;
    const float* Bg = B + (size_t)kOff * ldb;

    const int tid = threadIdx.x;
    const int lane = tid & 31, warp = tid >> 5;
    const int wm = warp & 3, wn = warp >> 2;
    const int g4 = lane >> 2, l4 = lane & 3;

    float acc[2][4][4] = {};
    float4 pa[4], pb[2];

    const int ar = tid >> 3, ak4 = (tid & 7) * 4;
    const int bkp = tid >> 4, bn4 = (tid & 15) * 4;

    const int aRow = lane & 15;
    const uint32_t aHiB = ((lane >> 4) & 1) * 16;
    const uint32_t adAh = sm_u32(Ah) + (uint32_t)((wm * 32 + aRow) * PPA) * 4 + aHiB;
    const uint32_t adAl = sm_u32(Al) + (uint32_t)((wm * 32 + aRow) * PPA) * 4 + aHiB;
    const int bRowN = ((lane >> 4) & 1) * 8 + (lane & 7);
    const uint32_t bHiB = ((lane >> 3) & 1) * 16;
    const uint32_t adBh0 = sm_u32(Bh) + (uint32_t)boff(wn * 32 + bRowN) * 4 + bHiB;
    const uint32_t adBh1 = sm_u32(Bh) + (uint32_t)boff(wn * 32 + 16 + bRowN) * 4 + bHiB;
    const uint32_t adBl0 = sm_u32(Bl) + (uint32_t)boff(wn * 32 + bRowN) * 4 + bHiB;
    const uint32_t adBl1 = sm_u32(Bl) + (uint32_t)boff(wn * 32 + 16 + bRowN) * 4 + bHiB;

    auto loadA = [&](int k0) {
        #pragma unroll
        for (int p = 0; p < 4; p++) {
            int row = bm + p * 32 + ar;
            float4 v = make_float4(0.f, 0.f, 0.f, 0.f);
            if (row < M) v = *reinterpret_cast<const float4*>(Ag + (size_t)row * lda + k0 + ak4);
            pa[p] = v;
        }
    };
    auto loadB = [&](int k0) {
        pb[0] = *reinterpret_cast<const float4*>(Bg + (size_t)(k0 + 2 * bkp) * ldb + bn + bn4);
        pb[1] = *reinterpret_cast<const float4*>(Bg + (size_t)(k0 + 2 * bkp + 1) * ldb + bn + bn4);
    };
    auto storeAB = [&](int s) {
        uint32_t* AhS = Ah + s * ABUF;
        uint32_t* AlS = Al + s * ABUF;
        uint32_t* BhS = Bh + s * BPLANE;
        uint32_t* BlS = Bl + s * BPLANE;
        #pragma unroll
        for (int p = 0; p < 4; p++) {
            int row = p * 32 + ar;
            uint32_t h0, l0, h1, l1;
            split2(pa[p].x, pa[p].y, h0, l0);
            split2(pa[p].z, pa[p].w, h1, l1);
            int wi = row * PPA + (ak4 >> 1);
            AhS[wi] = h0; AhS[wi + 1] = h1;
            AlS[wi] = l0; AlS[wi + 1] = l1;
        }
        const float* p0 = &pb[0].x;
        const float* p1 = &pb[1].x;
        #pragma unroll
        for (int i = 0; i < 4; i++) {
            uint32_t hw, lw;
            split2(p0[i], p1[i], hw, lw);   // low = even k
            int wi = boff(bn4 + i) + bkp;
            BhS[wi] = hw; BlS[wi] = lw;
        }
    };

    loadA(0);
    loadB(0);
    storeAB(0);
    __syncthreads();

    int s = 0;
    for (int k0 = 0; k0 < Ksub; k0 += 32) {
        const bool more = (k0 + 32 < Ksub);
        if (more) { loadA(k0 + 32); loadB(k0 + 32); }

        const uint32_t aOffB = (uint32_t)s * (ABUF * 4);
        const uint32_t bOffB = (uint32_t)s * (BPLANE * 4);
        #pragma unroll
        for (int ks = 0; ks < 2; ks++) {
            uint32_t ahh[2][4], alo[2][4];
            ldsm4(ahh[0], adAh + aOffB + ks * 32);
            ldsm4(ahh[1], adAh + aOffB + 16 * PPA * 4 + ks * 32);
            ldsm4(alo[0], adAl + aOffB + ks * 32);
            ldsm4(alo[1], adAl + aOffB + 16 * PPA * 4 + ks * 32);
            uint32_t bhh[2][4], blo[2][4];
            ldsm4(bhh[0], adBh0 + bOffB + ks * 32);
            ldsm4(bhh[1], adBh1 + bOffB + ks * 32);
            ldsm4(blo[0], adBl0 + bOffB + ks * 32);
            ldsm4(blo[1], adBl1 + bOffB + ks * 32);
            #pragma unroll
            for (int am = 0; am < 2; am++)
                #pragma unroll
                for (int an = 0; an < 4; an++) {
                    const int g = an >> 1, x = (an & 1) * 2;
                    mma16(acc[am][an], ahh[am], bhh[g][x], bhh[g][x + 1]);
                    mma16(acc[am][an], ahh[am], blo[g][x], blo[g][x + 1]);
                    mma16(acc[am][an], alo[am], bhh[g][x], bhh[g][x + 1]);
                }
        }
        if (more) storeAB(s ^ 1);
        __syncthreads();
        s ^= 1;
    }

    #pragma unroll
    for (int am = 0; am < 2; am++) {
        int row0 = bm + wm * 32 + am * 16 + g4;
        #pragma unroll
        for (int an = 0; an < 4; an++) {
            int col0 = bn + wn * 32 + an * 8 + 2 * l4;
            float v0 = acc[am][an][0], v1 = acc[am][an][1];
            float v2 = acc[am][an][2], v3 = acc[am][an][3];
            if (cbias && blockIdx.z == 0) {
                float b0 = cbias[col0], b1 = cbias[col0 + 1];
                v0 += b0; v1 += b1; v2 += b0; v3 += b1;
            }
            if (doRelu) {
                v0 = fmaxf(v0, 0.f); v1 = fmaxf(v1, 0.f);
                v2 = fmaxf(v2, 0.f); v3 = fmaxf(v3, 0.f);
            }
            if (row0 < M) {
                C[(size_t)row0 * ldc + col0]     = v0;
                C[(size_t)row0 * ldc + col0 + 1] = v1;
            }
            if (row0 + 8 < M) {
                C[(size_t)(row0 + 8) * ldc + col0]     = v2;
                C[(size_t)(row0 + 8) * ldc + col0 + 1] = v3;
            }
        }
    }
}

// ---------------- fused flash-style relative attention (bf16x3 + ldmatrix + KV prefetch) ----------------
#define RPAD 68
#define RSLOT (64 * RPAD)
#define ATTN_WORDS (12 * BPLANE + 3 * RSLOT + 256)
#define ATTN_SMEM (ATTN_WORDS * 4)

__global__ __launch_bounds__(256, 1)
void fused_attn_kernel(const float* __restrict__ heads,
                       const float* __restrict__ rbuf,
                       const float* __restrict__ rwb,
                       const float* __restrict__ rrb,
                       float* __restrict__ av) {
    extern __shared__ uint32_t smu[];
    uint32_t* Qwh = smu;
    uint32_t* Qwl = Qwh + BPLANE;
    uint32_t* Qrh = Qwl + BPLANE;
    uint32_t* Qrl = Qrh + BPLANE;
    uint32_t* Kh  = Qrl + BPLANE;
    uint32_t* Kl  = Kh  + BPLANE;
    uint32_t* Rh  = Kl  + BPLANE;
    uint32_t* Rl  = Rh  + BPLANE;
    uint32_t* Vth = Rl  + BPLANE;
    uint32_t* Vtl = Vth + BPLANE;
    uint32_t* Ph  = Vtl + BPLANE;
    uint32_t* Pl  = Ph  + BPLANE;
    float* Ring = (float*)(Pl + BPLANE);
    float* redm = Ring + 3 * RSLOT;
    float* reds = redm + 128;

    const int h = blockIdx.x;
    const int p = blockIdx.y;
    const int tid = threadIdx.x;
    const int lane = tid & 31, warp = tid >> 5;
    const int wm = warp & 3, wn = warp >> 2;
    const int g4 = lane >> 2, l4 = lane & 3;
    const int wr0 = wm * 16 + g4;
    const int colbase = wn * 32;

    const int aRow = lane & 15;
    const uint32_t aHiB = ((lane >> 4) & 1) * 16;
    const uint32_t aOff = (uint32_t)boff(wm * 16 + aRow) * 4 + aHiB;
    const uint32_t adQwh = sm_u32(Qwh) + aOff, adQwl = sm_u32(Qwl) + aOff;
    const uint32_t adQrh = sm_u32(Qrh) + aOff, adQrl = sm_u32(Qrl) + aOff;
    const uint32_t adPh  = sm_u32(Ph)  + aOff, adPl  = sm_u32(Pl)  + aOff;
    const int bRowN = ((lane >> 4) & 1) * 8 + (lane & 7);
    const uint32_t bHiB = ((lane >> 3) & 1) * 16;
    const uint32_t bO0 = (uint32_t)boff(colbase + bRowN) * 4 + bHiB;
    const uint32_t bO1 = (uint32_t)boff(colbase + 16 + bRowN) * 4 + bHiB;
    const uint32_t adKh0 = sm_u32(Kh) + bO0,  adKh1 = sm_u32(Kh) + bO1;
    const uint32_t adKl0 = sm_u32(Kl) + bO0,  adKl1 = sm_u32(Kl) + bO1;
    const uint32_t adRh0 = sm_u32(Rh) + bO0,  adRh1 = sm_u32(Rh) + bO1;
    const uint32_t adRl0 = sm_u32(Rl) + bO0,  adRl1 = sm_u32(Rl) + bO1;
    const uint32_t adVh0 = sm_u32(Vth) + bO0, adVh1 = sm_u32(Vth) + bO1;
    const uint32_t adVl0 = sm_u32(Vtl) + bO0, adVl1 = sm_u32(Vtl) + bO1;

    // KV prefetch registers + helpers
    float4 kreg[4], vreg[4];
    const int kvr = tid >> 4, kvc4 = (tid & 15) * 4;
    const int vkp = tid >> 3, vfb = (tid & 7) * 8;
    auto prefetchKV = [&](int j0) {
        #pragma unroll
        for (int it = 0; it < 4; it++) {
            int grow = j0 + kvr + 16 * it;
            kreg[it] = make_float4(0.f, 0.f, 0.f, 0.f);
            if (grow < TT)
                kreg[it] = *(const float4*)(heads + (size_t)grow * (3 * DM) + DM + h * DH + kvc4);
        }
        int jA = j0 + 2 * vkp, jB = jA + 1;
        vreg[0] = vreg[1] = vreg[2] = vreg[3] = make_float4(0.f, 0.f, 0.f, 0.f);
        if (jA < TT) {
            vreg[0] = *(const float4*)(heads + (size_t)jA * (3 * DM) + 2 * DM + h * DH + vfb);
            vreg[1] = *(const float4*)(heads + (size_t)jA * (3 * DM) + 2 * DM + h * DH + vfb + 4);
        }
        if (jB < TT) {
            vreg[2] = *(const float4*)(heads + (size_t)jB * (3 * DM) + 2 * DM + h * DH + vfb);
            vreg[3] = *(const float4*)(heads + (size_t)jB * (3 * DM) + 2 * DM + h * DH + vfb + 4);
        }
    };
    auto storeKV = [&]() {
        #pragma unroll
        for (int it = 0; it < 4; it++) {
            int wi = boff(kvr + 16 * it) + (kvc4 >> 1);
            uint32_t hw, lw;
            split2(kreg[it].x, kreg[it].y, hw, lw); Kh[wi] = hw;     Kl[wi] = lw;
            split2(kreg[it].z, kreg[it].w, hw, lw); Kh[wi + 1] = hw; Kl[wi + 1] = lw;
        }
        const float* pa0 = &vreg[0].x; const float* pa1 = &vreg[1].x;
        const float* pb0 = &vreg[2].x; const float* pb1 = &vreg[3].x;
        #pragma unroll
        for (int i = 0; i < 4; i++) {
            uint32_t hw, lw;
            split2(pa0[i], pb0[i], hw, lw);           // low = even key
            Vth[boff(vfb + i) + vkp] = hw; Vtl[boff(vfb + i) + vkp] = lw;
            split2(pa1[i], pb1[i], hw, lw);
            Vth[boff(vfb + 4 + i) + vkp] = hw; Vtl[boff(vfb + 4 + i) + vkp] = lw;
        }
    };

    int blist[2]; int nblk;
    if (p < 16) { blist[0] = p; blist[1] = 31 - p; nblk = 2; }
    else        { blist[0] = 32; nblk = 1; }

    for (int bi = 0; bi < nblk; bi++) {
        const int b = blist[bi];
        const int i0 = b * 64;
        const int validRows = min(64, TT - i0);
        const int njt = (b < 32) ? (b + 1) : 33;

        __syncthreads();
        // Load Q (+ biases), pre-split into pair planes
        for (int t = tid; t < 64 * 16; t += 256) {
            int r = t >> 4, c4 = (t & 15) * 4;
            int grow = i0 + r;
            float4 q = make_float4(0.f, 0.f, 0.f, 0.f);
            if (grow < TT)
                q = *(const float4*)(heads + (size_t)grow * (3 * DM) + h * DH + c4);
            float4 bw = *(const float4*)(rwb + h * DH + c4);
            float4 br = *(const float4*)(rrb + h * DH + c4);
            int wi = boff(r) + (c4 >> 1);
            uint32_t hw, lw;
            split2(q.x + bw.x, q.y + bw.y, hw, lw); Qwh[wi] = hw;     Qwl[wi] = lw;
            split2(q.z + bw.z, q.w + bw.w, hw, lw); Qwh[wi + 1] = hw; Qwl[wi + 1] = lw;
            split2(q.x + br.x, q.y + br.y, hw, lw); Qrh[wi] = hw;     Qrl[wi] = lw;
            split2(q.z + br.z, q.w + br.w, hw, lw); Qrh[wi + 1] = hw; Qrl[wi + 1] = lw;
        }
        prefetchKV(0);

        float o[4][4];
        #pragma unroll
        for (int a = 0; a < 4; a++) { o[a][0] = o[a][1] = o[a][2] = o[a][3] = 0.f; }
        float mrow[2] = {-1e30f, -1e30f};
        float lrow[2] = {0.f, 0.f};

        int nextChunk = (2016 - i0) / 64;
        if (nextChunk < 0) nextChunk = 0;

        for (int jt = 0; jt < njt; jt++) {
            const int j0 = jt * 64;

            // ---- build BDraw chunks ----
            const int hiJr = min(TT - 1, TT - 1 - i0 + j0 + 63);
            const int chi = hiJr >> 6;
            while (nextChunk <= chi) {
                const int c = nextChunk;
                __syncthreads();
                for (int t = tid; t < 64 * 16; t += 256) {
                    int r = t >> 4, c4 = (t & 15) * 4;
                    int grow = c * 64 + r;
                    float4 v = make_float4(0.f, 0.f, 0.f, 0.f);
                    if (grow < TT)
                        v = *(const float4*)(rbuf + (size_t)grow * DM + h * DH + c4);
                    int wi = boff(r) + (c4 >> 1);
                    uint32_t hw, lw;
                    split2(v.x, v.y, hw, lw); Rh[wi] = hw;     Rl[wi] = lw;
                    split2(v.z, v.w, hw, lw); Rh[wi + 1] = hw; Rl[wi + 1] = lw;
                }
                __syncthreads();
                float cacc[4][4];
                #pragma unroll
                for (int a = 0; a < 4; a++)
                    cacc[a][0] = cacc[a][1] = cacc[a][2] = cacc[a][3] = 0.f;
                #pragma unroll
                for (int kc = 0; kc < 4; kc++) {
                    uint32_t ah[4], al[4];
                    ldsm4(ah, adQrh + kc * 32);
                    ldsm4(al, adQrl + kc * 32);
                    uint32_t bh[2][4], bl[2][4];
                    ldsm4(bh[0], adRh0 + kc * 32);
                    ldsm4(bh[1], adRh1 + kc * 32);
                    ldsm4(bl[0], adRl0 + kc * 32);
                    ldsm4(bl[1], adRl1 + kc * 32);
                    #pragma unroll
                    for (int an = 0; an < 4; an++) {
                        const int g = an >> 1, x = (an & 1) * 2;
                        mma16(cacc[an], ah, bh[g][x], bh[g][x + 1]);
                        mma16(cacc[an], ah, bl[g][x], bl[g][x + 1]);
                        mma16(cacc[an], al, bh[g][x], bh[g][x + 1]);
                    }
                }
                float* slot = Ring + (c % 3) * RSLOT;
                #pragma unroll
                for (int an = 0; an < 4; an++) {
                    int col = colbase + an * 8 + 2 * l4;
                    slot[wr0 * RPAD + col]           = cacc[an][0];
                    slot[wr0 * RPAD + col + 1]       = cacc[an][1];
                    slot[(wr0 + 8) * RPAD + col]     = cacc[an][2];
                    slot[(wr0 + 8) * RPAD + col + 1] = cacc[an][3];
                }
                nextChunk++;
            }

            // ---- store prefetched K/V tile into smem planes ----
            __syncthreads();
            storeKV();
            __syncthreads();

            // ---- AC MMA ----
            float s[4][4];
            #pragma unroll
            for (int a = 0; a < 4; a++)
                s[a][0] = s[a][1] = s[a][2] = s[a][3] = 0.f;
            #pragma unroll
            for (int kc = 0; kc < 4; kc++) {
                uint32_t ah[4], al[4];
                ldsm4(ah, adQwh + kc * 32);
                ldsm4(al, adQwl + kc * 32);
                uint32_t bh[2][4], bl[2][4];
                ldsm4(bh[0], adKh0 + kc * 32);
                ldsm4(bh[1], adKh1 + kc * 32);
                ldsm4(bl[0], adKl0 + kc * 32);
                ldsm4(bl[1], adKl1 + kc * 32);
                #pragma unroll
                for (int an = 0; an < 4; an++) {
                    const int g = an >> 1, x = (an & 1) * 2;
                    mma16(s[an], ah, bh[g][x], bh[g][x + 1]);
                    mma16(s[an], ah, bl[g][x], bl[g][x + 1]);
                    mma16(s[an], al, bh[g][x], bh[g][x + 1]);
                }
            }

            // ---- combine with rel-shifted BD + mask + scale ----
            float tmax[2] = {-1e30f, -1e30f};
            #pragma unroll
            for (int an = 0; an < 4; an++) {
                #pragma unroll
                for (int e = 0; e < 4; e++) {
                    int rh = e >> 1;
                    int di = wr0 + rh * 8;
                    int dj = colbase + an * 8 + 2 * l4 + (e & 1);
                    int i = i0 + di, j = j0 + dj;
                    float v = -1e30f;
                    if (di < validRows && j < TT) {
                        int jmaxr = (i < NMTOK) ? (NMTOK - 1)
                                  : ((i >= TT - NMTOK) ? (TT - 1) : i);
                        if (j <= jmaxr) {
                            float bd;
                            if (j <= i) {
                                int jr = TT - 1 - i + j;
                                bd = Ring[((jr >> 6) % 3) * RSLOT + di * RPAD + (jr & 63)];
                            } else if (j == i + 1) {
                                bd = 0.f;
                            } else {
                                const float* rr = rbuf + (size_t)(j - i - 2) * DM + h * DH;
                                float accd = 0.f;
                                #pragma unroll 8
                                for (int d2 = 0; d2 < 32; d2++) {
                                    uint32_t wh = Qrh[boff(di + 1) + d2];
                                    uint32_t wl = Qrl[boff(di + 1) + d2];
                                    __nv_bfloat162 h2 = *reinterpret_cast<__nv_bfloat162*>(&wh);
                                    __nv_bfloat162 l2 = *reinterpret_cast<__nv_bfloat162*>(&wl);
                                    float q0 = __bfloat162float(h2.x) + __bfloat162float(l2.x);
                                    float q1 = __bfloat162float(h2.y) + __bfloat162float(l2.y);
                                    accd += q0 * rr[2 * d2] + q1 * rr[2 * d2 + 1];
                                }
                                bd = accd;
                            }
                            v = (s[an][e] + bd) * 0.125f;
                        }
                    }
                    s[an][e] = v;
                    tmax[rh] = fmaxf(tmax[rh], v);
                }
            }
            #pragma unroll
            for (int rh = 0; rh < 2; rh++) {
                tmax[rh] = fmaxf(tmax[rh], __shfl_xor_sync(0xffffffffu, tmax[rh], 1));
                tmax[rh] = fmaxf(tmax[rh], __shfl_xor_sync(0xffffffffu, tmax[rh], 2));
            }
            if (l4 == 0) {
                redm[wn * 64 + wm * 16 + g4]     = tmax[0];
                redm[wn * 64 + wm * 16 + g4 + 8] = tmax[1];
            }
            __syncthreads();

            float scl[2], lsum[2] = {0.f, 0.f};
            #pragma unroll
            for (int rh = 0; rh < 2; rh++) {
                int row = wm * 16 + g4 + rh * 8;
                float tm = fmaxf(redm[row], redm[64 + row]);
                float mnew = fmaxf(mrow[rh], tm);
                scl[rh] = expf(mrow[rh] - mnew);
                mrow[rh] = mnew;
            }
            #pragma unroll
            for (int an = 0; an < 4; an++) {
                #pragma unroll
                for (int e = 0; e < 4; e++) {
                    int rh = e >> 1;
                    float ev = expf(s[an][e] - mrow[rh]);
                    s[an][e] = ev;
                    lsum[rh] += ev;
                }
            }
            #pragma unroll
            for (int rh = 0; rh < 2; rh++) {
                lsum[rh] += __shfl_xor_sync(0xffffffffu, lsum[rh], 1);
                lsum[rh] += __shfl_xor_sync(0xffffffffu, lsum[rh], 2);
            }
            if (l4 == 0) {
                reds[wn * 64 + wm * 16 + g4]     = lsum[0];
                reds[wn * 64 + wm * 16 + g4 + 8] = lsum[1];
            }
            // stage P into packed pair planes
            #pragma unroll
            for (int an = 0; an < 4; an++) {
                int cp = (colbase >> 1) + an * 4 + l4;
                uint32_t hw, lw;
                split2(s[an][0], s[an][1], hw, lw);
                Ph[boff(wr0) + cp] = hw; Pl[boff(wr0) + cp] = lw;
                split2(s[an][2], s[an][3], hw, lw);
                Ph[boff(wr0 + 8) + cp] = hw; Pl[boff(wr0 + 8) + cp] = lw;
            }
            __syncthreads();

            #pragma unroll
            for (int rh = 0; rh < 2; rh++) {
                int row = wm * 16 + g4 + rh * 8;
                lrow[rh] = lrow[rh] * scl[rh] + reds[row] + reds[64 + row];
            }
            #pragma unroll
            for (int an = 0; an < 4; an++) {
                o[an][0] *= scl[0]; o[an][1] *= scl[0];
                o[an][2] *= scl[1]; o[an][3] *= scl[1];
            }

            // ---- PV MMA ----
            #pragma unroll
            for (int kc = 0; kc < 4; kc++) {
                uint32_t ah[4], al[4];
                ldsm4(ah, adPh + kc * 32);
                ldsm4(al, adPl + kc * 32);
                uint32_t bh[2][4], bl[2][4];
                ldsm4(bh[0], adVh0 + kc * 32);
                ldsm4(bh[1], adVh1 + kc * 32);
                ldsm4(bl[0], adVl0 + kc * 32);
                ldsm4(bl[1], adVl1 + kc * 32);
                #pragma unroll
                for (int an = 0; an < 4; an++) {
                    const int g = an >> 1, x = (an & 1) * 2;
                    mma16(o[an], ah, bh[g][x], bh[g][x + 1]);
                    mma16(o[an], ah, bl[g][x], bl[g][x + 1]);
                    mma16(o[an], al, bh[g][x], bh[g][x + 1]);
                }
            }

            // prefetch next tile's K/V (latency hidden behind next BD/AC work)
            if (jt + 1 < njt) prefetchKV((jt + 1) * 64);
        } // j-tiles

        float inv0 = 1.f / lrow[0], inv1 = 1.f / lrow[1];
        #pragma unroll
        for (int an = 0; an < 4; an++) {
            int col = h * DH + colbase + an * 8 + 2 * l4;
            int r0 = i0 + wr0;
            if (wr0 < validRows) {
                av[(size_t)r0 * DM + col]     = o[an][0] * inv0;
                av[(size_t)r0 * DM + col + 1] = o[an][1] * inv0;
            }
            if (wr0 + 8 < validRows) {
                av[(size_t)(r0 + 8) * DM + col]     = o[an][2] * inv1;
                av[(size_t)(r0 + 8) * DM + col + 1] = o[an][3] * inv1;
            }
        }
    } // blocks
}

// ---------------- residual add + layernorm (optional second delta) ----------------
__global__ void add_ln_kernel(float* __restrict__ w, const float* __restrict__ delta,
                              const float* __restrict__ delta2,
                              const float* __restrict__ gam, const float* __restrict__ bta) {
    int row = blockIdx.x;
    int tid = threadIdx.x;
    __shared__ float red[256];
    float x0 = w[row * DM + tid]       + delta[row * DM + tid];
    float x1 = w[row * DM + tid + 256] + delta[row * DM + tid + 256];
    if (delta2) {
        x0 += delta2[row * DM + tid];
        x1 += delta2[row * DM + tid + 256];
    }
    red[tid] = x0 + x1; __syncthreads();
    for (int s = 128; s > 0; s >>= 1) {
        if (tid < s) red[tid] += red[tid + s];
        __syncthreads();
    }
    float mean = red[0] * (1.f / DM);
    __syncthreads();
    float d0 = x0 - mean, d1 = x1 - mean;
    red[tid] = d0 * d0 + d1 * d1; __syncthreads();
    for (int s = 128; s > 0; s >>= 1) {
        if (tid < s) red[tid] += red[tid + s];
        __syncthreads();
    }
    float inv = 1.f / sqrtf(red[0] * (1.f / DM) + 1e-5f);
    w[row * DM + tid]       = d0 * inv * gam[tid]       + bta[tid];
    w[row * DM + tid + 256] = d1 * inv * gam[tid + 256] + bta[tid + 256];
}

__global__ void copy_out_kernel(float* __restrict__ out) {
    int idx = blockIdx.x * blockDim.x + threadIdx.x;
    if (idx < TT * DM) out[idx] = g_w[idx];
}

// ---------------- launcher ----------------
extern "C" void kernel_launch(void* const* d_in, const int* in_sizes, int n_in,
                              void* d_out, int out_size) {
    (void)in_sizes; (void)n_in; (void)out_size;
    const float* word_emb = (const float*)d_in[0];
    const float* mem_tok  = (const float*)d_in[1];
    const float* Wqkv     = (const float*)d_in[2];
    const float* Wr       = (const float*)d_in[3];
    const float* Wo       = (const float*)d_in[4];
    const float* ln1s     = (const float*)d_in[5];
    const float* ln1b     = (const float*)d_in[6];
    const float* W1       = (const float*)d_in[7];
    const float* b1       = (const float*)d_in[8];
    const float* W2       = (const float*)d_in[9];
    const float* b2       = (const float*)d_in[10];
    const float* ln2s     = (const float*)d_in[11];
    const float* ln2b     = (const float*)d_in[12];
    const float* rwb      = (const float*)d_in[13];
    const float* rrb      = (const float*)d_in[14];

    float *g_w_p, *g_pos_p, *g_hd_p, *g_r_p, *g_av_p, *g_tmp_p, *g_tmp2_p, *g_ff1_p;
    cudaGetSymbolAddress((void**)&g_w_p,    g_w);
    cudaGetSymbolAddress((void**)&g_pos_p,  g_pos);
    cudaGetSymbolAddress((void**)&g_hd_p,   g_heads);
    cudaGetSymbolAddress((void**)&g_r_p,    g_r);
    cudaGetSymbolAddress((void**)&g_av_p,   g_av);
    cudaGetSymbolAddress((void**)&g_tmp_p,  g_tmp);
    cudaGetSymbolAddress((void**)&g_tmp2_p, g_tmp2);
    cudaGetSymbolAddress((void**)&g_ff1_p,  g_ff1);

    cudaFuncSetAttribute(fused_attn_kernel,
                         cudaFuncAttributeMaxDynamicSharedMemorySize, ATTN_SMEM);
    cudaFuncSetAttribute(mma_gemm,
                         cudaFuncAttributeMaxDynamicSharedMemorySize, GEMM_SMEM);

    const int TD = TT * DM;
    build_w_kernel<<<(TD + 255) / 256, 256>>>(word_emb, mem_tok);
    build_pos_kernel<<<(TD + 255) / 256, 256>>>();

    const int MB = (TT + 127) / 128;   // 17

    for (int l = 0; l < NLAY; l++) {
        // QKV: heads = w @ Wqkv[l]
        mma_gemm<<<dim3(3 * DM / 64, MB, 1), 256, GEMM_SMEM>>>(
            g_w_p, DM, Wqkv + (size_t)l * DM * 3 * DM, 3 * DM,
            g_hd_p, g_hd_p, 3 * DM, nullptr, 0, TT, 3 * DM, DM);
        // Wr: r = pos @ Wr[l]
        mma_gemm<<<dim3(DM / 64, MB, 1), 256, GEMM_SMEM>>>(
            g_pos_p, DM, Wr + (size_t)l * DM * DM, DM,
            g_r_p, g_r_p, DM, nullptr, 0, TT, DM, DM);

        fused_attn_kernel<<<dim3(NH, 17), 256, ATTN_SMEM>>>(
            g_hd_p, g_r_p, rwb, rrb, g_av_p);

        // Wo: K-split over z (2 x 256)
        mma_gemm<<<dim3(DM / 64, MB, 2), 256, GEMM_SMEM>>>(
            g_av_p, DM, Wo + (size_t)l * DM * DM, DM,
            g_tmp_p, g_tmp2_p, DM, nullptr, 0, TT, DM, DM / 2);
        add_ln_kernel<<<TT, 256>>>(g_w_p, g_tmp_p, g_tmp2_p, ln1s + l * DM, ln1b + l * DM);
        // FFN1
        mma_gemm<<<dim3(DI / 64, MB, 1), 256, GEMM_SMEM>>>(
            g_w_p, DM, W1 + (size_t)l * DM * DI, DI,
            g_ff1_p, g_ff1_p, DI, b1 + (size_t)l * DI, 1, TT, DI, DM);
        // FFN2: K-split over z (2 x 1024)
        mma_gemm<<<dim3(DM / 64, MB, 2), 256, GEMM_SMEM>>>(
            g_ff1_p, DI, W2 + (size_t)l * DI * DM, DM,
            g_tmp_p, g_tmp2_p, DM, b2 + (size_t)l * DM, 0, TT, DM, DI / 2);
        add_ln_kernel<<<TT, 256>>>(g_w_p, g_tmp_p, g_tmp2_p, ln2s + l * DM, ln2b + l * DM);
    }

    copy_out_kernel<<<(TD + 255) / 256, 256>>>((float*)d_out);
}